// round 1
// baseline (speedup 1.0000x reference)
#include <cuda_runtime.h>
#include <math.h>

#define NN 100000
#define EE 1600000

// ---------------- scratch (device globals; no allocation allowed) ----------------
__device__ __align__(16) float g_xw1[NN * 64];   // x @ W1
__device__ __align__(16) float g_feat2[NN * 70]; // [h1(64) | xt(6)]
__device__ __align__(16) float g_xw2[NN * 80];   // feat2 @ W2
__device__ float g_s1src[NN * 8], g_s1dst[NN * 8];
__device__ float g_s2src[NN * 8], g_s2dst[NN * 8];
__device__ int g_deg[NN];
__device__ int g_rowptr[NN + 1];
__device__ int g_pos[NN];
__device__ int g_col[EE];
__device__ int g_bsum[128];

__device__ __forceinline__ float leaky(float a) { return a >= 0.f ? a : 0.2f * a; }

// ---------------- CSR build ----------------
__global__ void zero_deg_k() {
    int i = blockIdx.x * blockDim.x + threadIdx.x;
    if (i < NN) g_deg[i] = 0;
}

__global__ void hist_k(const int* __restrict__ ei, int E) {
    int e = blockIdx.x * blockDim.x + threadIdx.x;
    if (e >= E) return;
    int s = ei[e], d = ei[E + e];
    if (s != d) atomicAdd(&g_deg[d], 1);
}

__global__ void scan1_k() {
    int b = blockIdx.x, t = threadIdx.x;
    int base = b * 1024 + t * 4;
    int s = 0;
#pragma unroll
    for (int j = 0; j < 4; j++) {
        int i = base + j;
        if (i < NN) s += g_deg[i];
    }
    __shared__ int red[256];
    red[t] = s;
    __syncthreads();
    for (int o = 128; o > 0; o >>= 1) {
        if (t < o) red[t] += red[t + o];
        __syncthreads();
    }
    if (t == 0) g_bsum[b] = red[0];
}

__global__ void scan2_k(int nb) {
    __shared__ int s[128];
    int t = threadIdx.x;
    s[t] = (t < nb) ? g_bsum[t] : 0;
    __syncthreads();
    if (t == 0) {
        int run = 0;
        for (int i = 0; i < nb; i++) { int v = s[i]; s[i] = run; run += v; }
        g_rowptr[NN] = run;
    }
    __syncthreads();
    if (t < nb) g_bsum[t] = s[t];
}

__global__ void scan3_k() {
    int b = blockIdx.x, t = threadIdx.x;
    int base = b * 1024 + t * 4;
    int v[4];
    int tot = 0;
#pragma unroll
    for (int j = 0; j < 4; j++) {
        int i = base + j;
        v[j] = (i < NN) ? g_deg[i] : 0;
        tot += v[j];
    }
    __shared__ int sc[256];
    sc[t] = tot;
    __syncthreads();
    for (int o = 1; o < 256; o <<= 1) {
        int x = (t >= o) ? sc[t - o] : 0;
        __syncthreads();
        sc[t] += x;
        __syncthreads();
    }
    int excl = sc[t] - tot + g_bsum[b];
#pragma unroll
    for (int j = 0; j < 4; j++) {
        int i = base + j;
        if (i < NN) { g_rowptr[i] = excl; g_pos[i] = excl; excl += v[j]; }
    }
}

__global__ void fill_k(const int* __restrict__ ei, int E) {
    int e = blockIdx.x * blockDim.x + threadIdx.x;
    if (e >= E) return;
    int s = ei[e], d = ei[E + e];
    if (s != d) {
        int slot = atomicAdd(&g_pos[d], 1);
        g_col[slot] = s;
    }
}

// ---------------- GEMM 1: xw1 = x @ W1  (N x 64 @ 64 x 64) ----------------
__global__ __launch_bounds__(256) void gemm1_k(const float* __restrict__ x,
                                               const float* __restrict__ W1) {
    __shared__ __align__(16) float sW[64 * 64];
    for (int i = threadIdx.x; i < 4096; i += 256) sW[i] = W1[i];
    __syncthreads();
    int lane = threadIdx.x & 31;
    int gw = (blockIdx.x * blockDim.x + threadIdx.x) >> 5;
    int nw = (gridDim.x * blockDim.x) >> 5;
    for (int n = gw; n < NN; n += nw) {
        float2 xr = *(const float2*)&x[n * 64 + lane * 2];
        float a0 = 0.f, a1 = 0.f;
#pragma unroll
        for (int k2 = 0; k2 < 32; k2++) {
            float xa = __shfl_sync(0xffffffffu, xr.x, k2);
            float xb = __shfl_sync(0xffffffffu, xr.y, k2);
            float2 w0 = *(const float2*)&sW[(2 * k2) * 64 + lane * 2];
            a0 += xa * w0.x; a1 += xa * w0.y;
            float2 w1 = *(const float2*)&sW[(2 * k2 + 1) * 64 + lane * 2];
            a0 += xb * w1.x; a1 += xb * w1.y;
        }
        *(float2*)&g_xw1[n * 64 + lane * 2] = make_float2(a0, a1);
    }
}

// ---------------- scores for GAT1 ----------------
__global__ void scores1_k(const float* __restrict__ att1) {
    int i = blockIdx.x * blockDim.x + threadIdx.x;
    if (i >= NN * 8) return;
    int node = i >> 3, h = i & 7;
    const float* xr = g_xw1 + node * 64 + h * 8;
    const float* ai = att1 + h * 16;
    float si = 0.f, sj = 0.f;
#pragma unroll
    for (int c = 0; c < 8; c++) { si += xr[c] * ai[c]; sj += xr[c] * ai[8 + c]; }
    g_s1dst[i] = si;
    g_s1src[i] = sj;
}

// ---------------- Encoder: warp per node ----------------
__device__ __forceinline__ void ln6(float* o, const float* swf, int goff, int boff) {
    float mu = (o[0] + o[1] + o[2] + o[3] + o[4] + o[5]) * (1.f / 6.f);
    float d0 = o[0] - mu, d1 = o[1] - mu, d2 = o[2] - mu, d3 = o[3] - mu, d4 = o[4] - mu, d5 = o[5] - mu;
    float var = (d0 * d0 + d1 * d1 + d2 * d2 + d3 * d3 + d4 * d4 + d5 * d5) * (1.f / 6.f);
    float rs = rsqrtf(var + 1e-5f);
    o[0] = d0 * rs * swf[goff + 0] + swf[boff + 0];
    o[1] = d1 * rs * swf[goff + 1] + swf[boff + 1];
    o[2] = d2 * rs * swf[goff + 2] + swf[boff + 2];
    o[3] = d3 * rs * swf[goff + 3] + swf[boff + 3];
    o[4] = d4 * rs * swf[goff + 4] + swf[boff + 4];
    o[5] = d5 * rs * swf[goff + 5] + swf[boff + 5];
}

// smem weight layout (floats):
// 0: WQp [10][8], 80: WKp [10][8], 160: WVp [10][8]
// 240: WF1 [6][24], 384: WF2p [24][8]
// 576: bq, 582: bk, 588: bv, 594: g0, 600: be0, 606: bf1[24], 630: bf2,
// 636: g1, 642: be1, 648: Wrep[32], 680: brep
__global__ __launch_bounds__(256) void encoder_k(
    const float* __restrict__ ef,
    const float* __restrict__ Wq, const float* __restrict__ bq,
    const float* __restrict__ Wk, const float* __restrict__ bk,
    const float* __restrict__ Wv, const float* __restrict__ bv,
    const float* __restrict__ g0, const float* __restrict__ be0,
    const float* __restrict__ Wf1, const float* __restrict__ bf1,
    const float* __restrict__ Wf2, const float* __restrict__ bf2,
    const float* __restrict__ g1, const float* __restrict__ be1,
    const float* __restrict__ Wrep, const float* __restrict__ brep) {
    __shared__ __align__(16) float swf[688];
    __shared__ float4 sK[8][32][2];
    __shared__ float4 sV[8][32][2];
    int tid = threadIdx.x;
    for (int i = tid; i < 688; i += 256) swf[i] = 0.f;
    __syncthreads();
    for (int i = tid; i < 60; i += 256) {
        int kk = i / 6, j = i % 6;
        swf[kk * 8 + j] = Wq[i];
        swf[80 + kk * 8 + j] = Wk[i];
        swf[160 + kk * 8 + j] = Wv[i];
    }
    for (int i = tid; i < 144; i += 256) swf[240 + i] = Wf1[i];
    for (int i = tid; i < 144; i += 256) swf[384 + (i / 6) * 8 + (i % 6)] = Wf2[i];
    if (tid < 6) {
        swf[576 + tid] = bq[tid]; swf[582 + tid] = bk[tid]; swf[588 + tid] = bv[tid];
        swf[594 + tid] = g0[tid]; swf[600 + tid] = be0[tid]; swf[630 + tid] = bf2[tid];
        swf[636 + tid] = g1[tid]; swf[642 + tid] = be1[tid];
    }
    if (tid < 24) swf[606 + tid] = bf1[tid];
    if (tid < 32) swf[648 + tid] = Wrep[tid];
    if (tid == 0) swf[680] = brep[0];
    __syncthreads();

    int lane = tid & 31, w = tid >> 5;
    int gw = (blockIdx.x * blockDim.x + tid) >> 5;
    int nwarps = (gridDim.x * blockDim.x) >> 5;
    const float SCALE = 0.40824829046386307f; // 1/sqrt(6)

    for (int n = gw; n < NN; n += nwarps) {
        const float* xr = ef + (size_t)n * 320 + lane * 10;
        float2 p0 = *(const float2*)xr, p1 = *(const float2*)(xr + 2),
               p2 = *(const float2*)(xr + 4), p3 = *(const float2*)(xr + 6),
               p4 = *(const float2*)(xr + 8);
        float xa[10] = {p0.x, p0.y, p1.x, p1.y, p2.x, p2.y, p3.x, p3.y, p4.x, p4.y};
        float q[6], k[6], v[6];
#pragma unroll
        for (int j = 0; j < 6; j++) { q[j] = swf[576 + j]; k[j] = swf[582 + j]; v[j] = swf[588 + j]; }
#pragma unroll
        for (int kk = 0; kk < 10; kk++) {
            float xv = xa[kk];
            float4 a = *(const float4*)&swf[kk * 8], b4 = *(const float4*)&swf[kk * 8 + 4];
            q[0] += xv * a.x; q[1] += xv * a.y; q[2] += xv * a.z; q[3] += xv * a.w;
            q[4] += xv * b4.x; q[5] += xv * b4.y;
            float4 c = *(const float4*)&swf[80 + kk * 8], d4 = *(const float4*)&swf[80 + kk * 8 + 4];
            k[0] += xv * c.x; k[1] += xv * c.y; k[2] += xv * c.z; k[3] += xv * c.w;
            k[4] += xv * d4.x; k[5] += xv * d4.y;
            float4 e4 = *(const float4*)&swf[160 + kk * 8], f4 = *(const float4*)&swf[160 + kk * 8 + 4];
            v[0] += xv * e4.x; v[1] += xv * e4.y; v[2] += xv * e4.z; v[3] += xv * e4.w;
            v[4] += xv * f4.x; v[5] += xv * f4.y;
        }
        sK[w][lane][0] = make_float4(k[0], k[1], k[2], 0.f);
        sK[w][lane][1] = make_float4(k[3], k[4], k[5], 0.f);
        sV[w][lane][0] = make_float4(v[0], v[1], v[2], 0.f);
        sV[w][lane][1] = make_float4(v[3], v[4], v[5], 0.f);
        __syncwarp();
        float o[6];
#pragma unroll
        for (int h = 0; h < 2; h++) {
            float q0 = q[h * 3], q1 = q[h * 3 + 1], q2 = q[h * 3 + 2];
            float m = -INFINITY, l = 0.f, a0 = 0.f, a1 = 0.f, a2 = 0.f;
#pragma unroll
            for (int tp = 0; tp < 32; tp++) {
                float4 kk4 = sK[w][tp][h];
                float s = (q0 * kk4.x + q1 * kk4.y + q2 * kk4.z) * SCALE;
                float mn = fmaxf(m, s);
                float p = __expf(s - mn);
                float cr = __expf(m - mn);
                float4 vv = sV[w][tp][h];
                l = l * cr + p;
                a0 = a0 * cr + p * vv.x;
                a1 = a1 * cr + p * vv.y;
                a2 = a2 * cr + p * vv.z;
                m = mn;
            }
            float inv = 1.f / l;
            o[h * 3 + 0] = q0 + a0 * inv;
            o[h * 3 + 1] = q1 + a1 * inv;
            o[h * 3 + 2] = q2 + a2 * inv;
        }
        __syncwarp();
        ln6(o, swf, 594, 600);
        float hh_[24];
#pragma unroll
        for (int jj = 0; jj < 24; jj++) hh_[jj] = swf[606 + jj];
#pragma unroll
        for (int kk = 0; kk < 6; kk++) {
            float ov = o[kk];
            const float4* r = (const float4*)&swf[240 + kk * 24];
#pragma unroll
            for (int qq = 0; qq < 6; qq++) {
                float4 wv = r[qq];
                hh_[qq * 4 + 0] += ov * wv.x;
                hh_[qq * 4 + 1] += ov * wv.y;
                hh_[qq * 4 + 2] += ov * wv.z;
                hh_[qq * 4 + 3] += ov * wv.w;
            }
        }
#pragma unroll
        for (int jj = 0; jj < 24; jj++) hh_[jj] = fmaxf(hh_[jj], 0.f);
        float f[6];
#pragma unroll
        for (int j = 0; j < 6; j++) f[j] = swf[630 + j];
#pragma unroll
        for (int jj = 0; jj < 24; jj++) {
            float hv = hh_[jj];
            float4 lo = *(const float4*)&swf[384 + jj * 8];
            float4 hi = *(const float4*)&swf[384 + jj * 8 + 4];
            f[0] += hv * lo.x; f[1] += hv * lo.y; f[2] += hv * lo.z; f[3] += hv * lo.w;
            f[4] += hv * hi.x; f[5] += hv * hi.y;
        }
#pragma unroll
        for (int j = 0; j < 6; j++) o[j] += f[j];
        ln6(o, swf, 636, 642);
        float wr = swf[648 + lane];
        float brepv = swf[680];
#pragma unroll
        for (int j = 0; j < 6; j++) {
            float c = o[j] * wr;
            c += __shfl_xor_sync(0xffffffffu, c, 16);
            c += __shfl_xor_sync(0xffffffffu, c, 8);
            c += __shfl_xor_sync(0xffffffffu, c, 4);
            c += __shfl_xor_sync(0xffffffffu, c, 2);
            c += __shfl_xor_sync(0xffffffffu, c, 1);
            if (lane == 0) g_feat2[(size_t)n * 70 + 64 + j] = c + brepv;
        }
    }
}

// ---------------- GAT1 aggregation: warp per destination node ----------------
__global__ __launch_bounds__(256) void gat1_agg_k(const float* __restrict__ b1) {
    int gw = (blockIdx.x * blockDim.x + threadIdx.x) >> 5;
    if (gw >= NN) return;
    int lane = threadIdx.x & 31;
    int d = gw;
    int start = g_rowptr[d], deg = g_rowptr[d + 1] - start;
    int hl = lane & 7;
    float sdd = g_s1dst[d * 8 + hl];
    float aself = leaky(sdd + g_s1src[d * 8 + hl]);
    float m = aself;
    for (int base = 0; base < deg; base += 4) {
        int e = base + (lane >> 3);
        if (e < deg) {
            int s = g_col[start + e];
            m = fmaxf(m, leaky(sdd + g_s1src[s * 8 + hl]));
        }
    }
    m = fmaxf(m, __shfl_xor_sync(0xffffffffu, m, 8));
    m = fmaxf(m, __shfl_xor_sync(0xffffffffu, m, 16));
    float den = (lane < 8) ? __expf(aself - m) : 0.f;
    for (int base = 0; base < deg; base += 4) {
        int e = base + (lane >> 3);
        if (e < deg) {
            int s = g_col[start + e];
            den += __expf(leaky(sdd + g_s1src[s * 8 + hl]) - m);
        }
    }
    den += __shfl_xor_sync(0xffffffffu, den, 8);
    den += __shfl_xor_sync(0xffffffffu, den, 16);
    float invden = 1.f / den;
    int c0 = lane * 2;
    int hh = lane >> 2;
    float wse = __expf(aself - m) * invden; // per-lane head hl
    float wself = __shfl_sync(0xffffffffu, wse, hh);
    float2 xs = *(const float2*)&g_xw1[(size_t)d * 64 + c0];
    float acc0 = wself * xs.x, acc1 = wself * xs.y;
    for (int base = 0; base < deg; base += 32) {
        int sc = (base + lane < deg) ? g_col[start + base + lane] : 0;
        int nrem = min(32, deg - base);
        for (int i = 0; i < nrem; i++) {
            int s = __shfl_sync(0xffffffffu, sc, i);
            float we = __expf(leaky(sdd + g_s1src[s * 8 + hl]) - m) * invden;
            float wgt = __shfl_sync(0xffffffffu, we, hh);
            float2 xv = *(const float2*)&g_xw1[(size_t)s * 64 + c0];
            acc0 += wgt * xv.x;
            acc1 += wgt * xv.y;
        }
    }
    float v0 = acc0 + b1[c0], v1 = acc1 + b1[c0 + 1];
    v0 = v0 > 0.f ? v0 : (__expf(v0) - 1.f);
    v1 = v1 > 0.f ? v1 : (__expf(v1) - 1.f);
    g_feat2[(size_t)d * 70 + c0] = v0;
    g_feat2[(size_t)d * 70 + c0 + 1] = v1;
}

// ---------------- GEMM 2: xw2 = feat2 @ W2  (N x 70 @ 70 x 80) ----------------
__global__ __launch_bounds__(256) void gemm2_k(const float* __restrict__ W2) {
    __shared__ float sW[70 * 80];
    for (int i = threadIdx.x; i < 5600; i += 256) sW[i] = W2[i];
    __syncthreads();
    int lane = threadIdx.x & 31;
    int gw = (blockIdx.x * blockDim.x + threadIdx.x) >> 5;
    int nw = (gridDim.x * blockDim.x) >> 5;
    int c2 = 64 + (lane & 15);
    for (int n = gw; n < NN; n += nw) {
        const float* fr = &g_feat2[(size_t)n * 70];
        float f0 = fr[lane];
        float f1 = fr[32 + lane];
        float f2 = (lane < 6) ? fr[64 + lane] : 0.f;
        float a0 = 0.f, a1 = 0.f, a2 = 0.f;
#pragma unroll
        for (int kk = 0; kk < 32; kk++) {
            float xv = __shfl_sync(0xffffffffu, f0, kk);
            a0 += xv * sW[kk * 80 + lane];
            a1 += xv * sW[kk * 80 + 32 + lane];
            a2 += xv * sW[kk * 80 + c2];
        }
#pragma unroll
        for (int kk = 32; kk < 64; kk++) {
            float xv = __shfl_sync(0xffffffffu, f1, kk - 32);
            a0 += xv * sW[kk * 80 + lane];
            a1 += xv * sW[kk * 80 + 32 + lane];
            a2 += xv * sW[kk * 80 + c2];
        }
#pragma unroll
        for (int kk = 64; kk < 70; kk++) {
            float xv = __shfl_sync(0xffffffffu, f2, kk - 64);
            a0 += xv * sW[kk * 80 + lane];
            a1 += xv * sW[kk * 80 + 32 + lane];
            a2 += xv * sW[kk * 80 + c2];
        }
        g_xw2[(size_t)n * 80 + lane] = a0;
        g_xw2[(size_t)n * 80 + 32 + lane] = a1;
        if (lane < 16) g_xw2[(size_t)n * 80 + c2] = a2;
    }
}

// ---------------- scores for GAT2 ----------------
__global__ void scores2_k(const float* __restrict__ att2) {
    int i = blockIdx.x * blockDim.x + threadIdx.x;
    if (i >= NN * 8) return;
    int node = i >> 3, h = i & 7;
    const float* xr = g_xw2 + (size_t)node * 80 + h * 10;
    const float* ai = att2 + h * 20;
    float si = 0.f, sj = 0.f;
#pragma unroll
    for (int c = 0; c < 10; c++) { si += xr[c] * ai[c]; sj += xr[c] * ai[10 + c]; }
    g_s2dst[i] = si;
    g_s2src[i] = sj;
}

// ---------------- GAT2 aggregation + mean heads + log_softmax ----------------
__global__ __launch_bounds__(256) void gat2_agg_k(const float* __restrict__ b2,
                                                  float* __restrict__ out) {
    __shared__ float sacc[8][80];
    __shared__ float sval[8][16];
    int gw = (blockIdx.x * blockDim.x + threadIdx.x) >> 5;
    if (gw >= NN) return;
    int lane = threadIdx.x & 31;
    int w = (threadIdx.x >> 5);
    int d = gw;
    int start = g_rowptr[d], deg = g_rowptr[d + 1] - start;
    int hl = lane & 7;
    float sdd = g_s2dst[d * 8 + hl];
    float aself = leaky(sdd + g_s2src[d * 8 + hl]);
    float m = aself;
    for (int base = 0; base < deg; base += 4) {
        int e = base + (lane >> 3);
        if (e < deg) {
            int s = g_col[start + e];
            m = fmaxf(m, leaky(sdd + g_s2src[s * 8 + hl]));
        }
    }
    m = fmaxf(m, __shfl_xor_sync(0xffffffffu, m, 8));
    m = fmaxf(m, __shfl_xor_sync(0xffffffffu, m, 16));
    float den = (lane < 8) ? __expf(aself - m) : 0.f;
    for (int base = 0; base < deg; base += 4) {
        int e = base + (lane >> 3);
        if (e < deg) {
            int s = g_col[start + e];
            den += __expf(leaky(sdd + g_s2src[s * 8 + hl]) - m);
        }
    }
    den += __shfl_xor_sync(0xffffffffu, den, 8);
    den += __shfl_xor_sync(0xffffffffu, den, 16);
    float invden = 1.f / den;
    int h0 = lane / 10;
    int h1 = (lane + 32) / 10;
    int h2 = (lane + 64) / 10;
    int i2 = 64 + (lane & 15);
    float wse = __expf(aself - m) * invden;
    float ws0 = __shfl_sync(0xffffffffu, wse, h0);
    float ws1 = __shfl_sync(0xffffffffu, wse, h1);
    float ws2 = __shfl_sync(0xffffffffu, wse, h2);
    const float* xd = &g_xw2[(size_t)d * 80];
    float acc0 = ws0 * xd[lane];
    float acc1 = ws1 * xd[32 + lane];
    float acc2 = ws2 * xd[i2];
    for (int base = 0; base < deg; base += 32) {
        int sc = (base + lane < deg) ? g_col[start + base + lane] : 0;
        int nrem = min(32, deg - base);
        for (int i = 0; i < nrem; i++) {
            int s = __shfl_sync(0xffffffffu, sc, i);
            float we = __expf(leaky(sdd + g_s2src[s * 8 + hl]) - m) * invden;
            float w0 = __shfl_sync(0xffffffffu, we, h0);
            float w1 = __shfl_sync(0xffffffffu, we, h1);
            float w2 = __shfl_sync(0xffffffffu, we, h2);
            const float* xr = &g_xw2[(size_t)s * 80];
            acc0 += w0 * xr[lane];
            acc1 += w1 * xr[32 + lane];
            acc2 += w2 * xr[i2];
        }
    }
    sacc[w][lane] = acc0;
    sacc[w][32 + lane] = acc1;
    if (lane < 16) sacc[w][i2] = acc2;
    __syncwarp();
    if (lane < 10) {
        float s = 0.f;
#pragma unroll
        for (int h = 0; h < 8; h++) s += sacc[w][h * 10 + lane];
        sval[w][lane] = s * 0.125f + b2[lane];
    }
    __syncwarp();
    if (lane < 10) {
        float mx = -INFINITY;
#pragma unroll
        for (int c = 0; c < 10; c++) mx = fmaxf(mx, sval[w][c]);
        float se = 0.f;
#pragma unroll
        for (int c = 0; c < 10; c++) se += __expf(sval[w][c] - mx);
        out[(size_t)d * 10 + lane] = sval[w][lane] - mx - logf(se);
    }
}

// ---------------- launch ----------------
extern "C" void kernel_launch(void* const* d_in, const int* in_sizes, int n_in,
                              void* d_out, int out_size) {
    const float* x    = (const float*)d_in[0];
    const int*   ei   = (const int*)d_in[1];
    const float* ef   = (const float*)d_in[2];
    const float* W1   = (const float*)d_in[3];
    const float* att1 = (const float*)d_in[4];
    const float* b1   = (const float*)d_in[5];
    const float* W2   = (const float*)d_in[6];
    const float* att2 = (const float*)d_in[7];
    const float* b2   = (const float*)d_in[8];
    const float* Wq   = (const float*)d_in[9];
    const float* bq   = (const float*)d_in[10];
    const float* Wk   = (const float*)d_in[11];
    const float* bk   = (const float*)d_in[12];
    const float* Wv   = (const float*)d_in[13];
    const float* bv   = (const float*)d_in[14];
    const float* g0   = (const float*)d_in[15];
    const float* be0  = (const float*)d_in[16];
    const float* Wf1  = (const float*)d_in[17];
    const float* bf1  = (const float*)d_in[18];
    const float* Wf2  = (const float*)d_in[19];
    const float* bf2  = (const float*)d_in[20];
    const float* g1   = (const float*)d_in[21];
    const float* be1  = (const float*)d_in[22];
    const float* Wrep = (const float*)d_in[23];
    const float* brep = (const float*)d_in[24];
    float* out = (float*)d_out;
    int E = in_sizes[1] / 2;

    zero_deg_k<<<(NN + 255) / 256, 256>>>();
    hist_k<<<(E + 255) / 256, 256>>>(ei, E);
    scan1_k<<<(NN + 1023) / 1024, 256>>>();
    scan2_k<<<1, 128>>>((NN + 1023) / 1024);
    scan3_k<<<(NN + 1023) / 1024, 256>>>();
    fill_k<<<(E + 255) / 256, 256>>>(ei, E);

    gemm1_k<<<1184, 256>>>(x, W1);
    scores1_k<<<(NN * 8 + 255) / 256, 256>>>(att1);
    encoder_k<<<1184, 256>>>(ef, Wq, bq, Wk, bk, Wv, bv, g0, be0,
                             Wf1, bf1, Wf2, bf2, g1, be1, Wrep, brep);
    gat1_agg_k<<<(NN + 7) / 8, 256>>>(b1);
    gemm2_k<<<1184, 256>>>(W2);
    scores2_k<<<(NN * 8 + 255) / 256, 256>>>(att2);
    gat2_agg_k<<<(NN + 7) / 8, 256>>>(b2, out);
}

// round 2
// speedup vs baseline: 1.1128x; 1.1128x over previous
#include <cuda_runtime.h>
#include <math.h>

#define NN 100000
#define EE 1600000

// ---------------- scratch ----------------
__device__ __align__(16) float g_xw1[NN * 64];   // x @ W1
__device__ __align__(16) float g_feat2[NN * 70]; // [h1(64) | xt(6)]
__device__ __align__(16) float g_xw2[NN * 80];   // feat2 @ W2
__device__ float g_s1src[NN * 8], g_s1dst[NN * 8];
__device__ float g_s2src[NN * 8], g_s2dst[NN * 8];
__device__ int g_deg[NN];
__device__ int g_rowptr[NN + 1];
__device__ int g_pos[NN];
__device__ int g_col[EE];
__device__ int g_bsum[128];

__device__ __forceinline__ float leaky(float a) { return a >= 0.f ? a : 0.2f * a; }

// ---------------- CSR build ----------------
__global__ void zero_deg_k() {
    int i = blockIdx.x * blockDim.x + threadIdx.x;
    if (i < NN) g_deg[i] = 0;
}

__global__ void hist_k(const int* __restrict__ ei, int E) {
    int e = blockIdx.x * blockDim.x + threadIdx.x;
    if (e >= E) return;
    int s = ei[e], d = ei[E + e];
    if (s != d) atomicAdd(&g_deg[d], 1);
}

__global__ void scan1_k() {
    int b = blockIdx.x, t = threadIdx.x;
    int base = b * 1024 + t * 4;
    int s = 0;
#pragma unroll
    for (int j = 0; j < 4; j++) {
        int i = base + j;
        if (i < NN) s += g_deg[i];
    }
    __shared__ int red[256];
    red[t] = s;
    __syncthreads();
    for (int o = 128; o > 0; o >>= 1) {
        if (t < o) red[t] += red[t + o];
        __syncthreads();
    }
    if (t == 0) g_bsum[b] = red[0];
}

__global__ void scan2_k(int nb) {
    __shared__ int s[128];
    int t = threadIdx.x;
    s[t] = (t < nb) ? g_bsum[t] : 0;
    __syncthreads();
    if (t == 0) {
        int run = 0;
        for (int i = 0; i < nb; i++) { int v = s[i]; s[i] = run; run += v; }
        g_rowptr[NN] = run;
    }
    __syncthreads();
    if (t < nb) g_bsum[t] = s[t];
}

__global__ void scan3_k() {
    int b = blockIdx.x, t = threadIdx.x;
    int base = b * 1024 + t * 4;
    int v[4];
    int tot = 0;
#pragma unroll
    for (int j = 0; j < 4; j++) {
        int i = base + j;
        v[j] = (i < NN) ? g_deg[i] : 0;
        tot += v[j];
    }
    __shared__ int sc[256];
    sc[t] = tot;
    __syncthreads();
    for (int o = 1; o < 256; o <<= 1) {
        int x = (t >= o) ? sc[t - o] : 0;
        __syncthreads();
        sc[t] += x;
        __syncthreads();
    }
    int excl = sc[t] - tot + g_bsum[b];
#pragma unroll
    for (int j = 0; j < 4; j++) {
        int i = base + j;
        if (i < NN) { g_rowptr[i] = excl; g_pos[i] = excl; excl += v[j]; }
    }
}

__global__ void fill_k(const int* __restrict__ ei, int E) {
    int e = blockIdx.x * blockDim.x + threadIdx.x;
    if (e >= E) return;
    int s = ei[e], d = ei[E + e];
    if (s != d) {
        int slot = atomicAdd(&g_pos[d], 1);
        g_col[slot] = s;
    }
}

// ---------------- GEMM 1 + fused GAT1 attention scores ----------------
__global__ __launch_bounds__(256) void gemm1_k(const float* __restrict__ x,
                                               const float* __restrict__ W1,
                                               const float* __restrict__ att1) {
    __shared__ __align__(16) float sW[64 * 64];
    __shared__ float sAtt[128];
    for (int i = threadIdx.x; i < 4096; i += 256) sW[i] = W1[i];
    if (threadIdx.x < 128) sAtt[threadIdx.x] = att1[threadIdx.x];
    __syncthreads();
    int lane = threadIdx.x & 31;
    int gw = (blockIdx.x * blockDim.x + threadIdx.x) >> 5;
    int nw = (gridDim.x * blockDim.x) >> 5;
    int h = lane >> 2;          // head for this lane's 2 cols
    int cc = (lane & 3) * 2;    // col within head
    float ai0 = sAtt[h * 16 + cc],     ai1 = sAtt[h * 16 + cc + 1];
    float aj0 = sAtt[h * 16 + 8 + cc], aj1 = sAtt[h * 16 + 8 + cc + 1];
    for (int n = gw; n < NN; n += nw) {
        float2 xr = *(const float2*)&x[n * 64 + lane * 2];
        float a0 = 0.f, a1 = 0.f;
#pragma unroll
        for (int k2 = 0; k2 < 32; k2++) {
            float xa = __shfl_sync(0xffffffffu, xr.x, k2);
            float xb = __shfl_sync(0xffffffffu, xr.y, k2);
            float2 w0 = *(const float2*)&sW[(2 * k2) * 64 + lane * 2];
            a0 += xa * w0.x; a1 += xa * w0.y;
            float2 w1 = *(const float2*)&sW[(2 * k2 + 1) * 64 + lane * 2];
            a0 += xb * w1.x; a1 += xb * w1.y;
        }
        *(float2*)&g_xw1[n * 64 + lane * 2] = make_float2(a0, a1);
        float si = a0 * ai0 + a1 * ai1;
        float sj = a0 * aj0 + a1 * aj1;
        si += __shfl_xor_sync(0xffffffffu, si, 1);
        si += __shfl_xor_sync(0xffffffffu, si, 2);
        sj += __shfl_xor_sync(0xffffffffu, sj, 1);
        sj += __shfl_xor_sync(0xffffffffu, sj, 2);
        if ((lane & 3) == 0) {
            g_s1dst[n * 8 + h] = si;
            g_s1src[n * 8 + h] = sj;
        }
    }
}

// ---------------- Encoder: warp per node ----------------
__device__ __forceinline__ void ln6(float* o, const float* swf, int goff, int boff) {
    float mu = (o[0] + o[1] + o[2] + o[3] + o[4] + o[5]) * (1.f / 6.f);
    float d0 = o[0] - mu, d1 = o[1] - mu, d2 = o[2] - mu, d3 = o[3] - mu, d4 = o[4] - mu, d5 = o[5] - mu;
    float var = (d0 * d0 + d1 * d1 + d2 * d2 + d3 * d3 + d4 * d4 + d5 * d5) * (1.f / 6.f);
    float rs = rsqrtf(var + 1e-5f);
    o[0] = d0 * rs * swf[goff + 0] + swf[boff + 0];
    o[1] = d1 * rs * swf[goff + 1] + swf[boff + 1];
    o[2] = d2 * rs * swf[goff + 2] + swf[boff + 2];
    o[3] = d3 * rs * swf[goff + 3] + swf[boff + 3];
    o[4] = d4 * rs * swf[goff + 4] + swf[boff + 4];
    o[5] = d5 * rs * swf[goff + 5] + swf[boff + 5];
}

__global__ __launch_bounds__(256) void encoder_k(
    const float* __restrict__ ef,
    const float* __restrict__ Wq, const float* __restrict__ bq,
    const float* __restrict__ Wk, const float* __restrict__ bk,
    const float* __restrict__ Wv, const float* __restrict__ bv,
    const float* __restrict__ g0, const float* __restrict__ be0,
    const float* __restrict__ Wf1, const float* __restrict__ bf1,
    const float* __restrict__ Wf2, const float* __restrict__ bf2,
    const float* __restrict__ g1, const float* __restrict__ be1,
    const float* __restrict__ Wrep, const float* __restrict__ brep) {
    __shared__ __align__(16) float swf[688];
    __shared__ float4 sK[8][32][2];
    __shared__ float4 sV[8][32][2];
    int tid = threadIdx.x;
    for (int i = tid; i < 688; i += 256) swf[i] = 0.f;
    __syncthreads();
    for (int i = tid; i < 60; i += 256) {
        int kk = i / 6, j = i % 6;
        swf[kk * 8 + j] = Wq[i];
        swf[80 + kk * 8 + j] = Wk[i];
        swf[160 + kk * 8 + j] = Wv[i];
    }
    for (int i = tid; i < 144; i += 256) swf[240 + i] = Wf1[i];
    for (int i = tid; i < 144; i += 256) swf[384 + (i / 6) * 8 + (i % 6)] = Wf2[i];
    if (tid < 6) {
        swf[576 + tid] = bq[tid]; swf[582 + tid] = bk[tid]; swf[588 + tid] = bv[tid];
        swf[594 + tid] = g0[tid]; swf[600 + tid] = be0[tid]; swf[630 + tid] = bf2[tid];
        swf[636 + tid] = g1[tid]; swf[642 + tid] = be1[tid];
    }
    if (tid < 24) swf[606 + tid] = bf1[tid];
    if (tid < 32) swf[648 + tid] = Wrep[tid];
    if (tid == 0) swf[680] = brep[0];
    __syncthreads();

    int lane = tid & 31, w = tid >> 5;
    int gw = (blockIdx.x * blockDim.x + tid) >> 5;
    int nwarps = (gridDim.x * blockDim.x) >> 5;
    const float SCALE = 0.40824829046386307f; // 1/sqrt(6)

    for (int n = gw; n < NN; n += nwarps) {
        const float* xr = ef + (size_t)n * 320 + lane * 10;
        float2 p0 = *(const float2*)xr, p1 = *(const float2*)(xr + 2),
               p2 = *(const float2*)(xr + 4), p3 = *(const float2*)(xr + 6),
               p4 = *(const float2*)(xr + 8);
        float xa[10] = {p0.x, p0.y, p1.x, p1.y, p2.x, p2.y, p3.x, p3.y, p4.x, p4.y};
        float q[6], k[6], v[6];
#pragma unroll
        for (int j = 0; j < 6; j++) { q[j] = swf[576 + j]; k[j] = swf[582 + j]; v[j] = swf[588 + j]; }
#pragma unroll
        for (int kk = 0; kk < 10; kk++) {
            float xv = xa[kk];
            float4 a = *(const float4*)&swf[kk * 8], b4 = *(const float4*)&swf[kk * 8 + 4];
            q[0] += xv * a.x; q[1] += xv * a.y; q[2] += xv * a.z; q[3] += xv * a.w;
            q[4] += xv * b4.x; q[5] += xv * b4.y;
            float4 c = *(const float4*)&swf[80 + kk * 8], d4 = *(const float4*)&swf[80 + kk * 8 + 4];
            k[0] += xv * c.x; k[1] += xv * c.y; k[2] += xv * c.z; k[3] += xv * c.w;
            k[4] += xv * d4.x; k[5] += xv * d4.y;
            float4 e4 = *(const float4*)&swf[160 + kk * 8], f4 = *(const float4*)&swf[160 + kk * 8 + 4];
            v[0] += xv * e4.x; v[1] += xv * e4.y; v[2] += xv * e4.z; v[3] += xv * e4.w;
            v[4] += xv * f4.x; v[5] += xv * f4.y;
        }
        sK[w][lane][0] = make_float4(k[0], k[1], k[2], 0.f);
        sK[w][lane][1] = make_float4(k[3], k[4], k[5], 0.f);
        sV[w][lane][0] = make_float4(v[0], v[1], v[2], 0.f);
        sV[w][lane][1] = make_float4(v[3], v[4], v[5], 0.f);
        __syncwarp();
        float o[6];
#pragma unroll
        for (int h = 0; h < 2; h++) {
            float q0 = q[h * 3], q1 = q[h * 3 + 1], q2 = q[h * 3 + 2];
            // logits are O(1): plain exp-sum softmax, no running max needed
            float l = 0.f, a0 = 0.f, a1 = 0.f, a2 = 0.f;
#pragma unroll
            for (int tp = 0; tp < 32; tp++) {
                float4 kk4 = sK[w][tp][h];
                float s = (q0 * kk4.x + q1 * kk4.y + q2 * kk4.z) * SCALE;
                float p = __expf(s);
                float4 vv = sV[w][tp][h];
                l += p;
                a0 += p * vv.x;
                a1 += p * vv.y;
                a2 += p * vv.z;
            }
            float inv = 1.f / l;
            o[h * 3 + 0] = q0 + a0 * inv;
            o[h * 3 + 1] = q1 + a1 * inv;
            o[h * 3 + 2] = q2 + a2 * inv;
        }
        __syncwarp();
        ln6(o, swf, 594, 600);
        float hh_[24];
#pragma unroll
        for (int jj = 0; jj < 24; jj++) hh_[jj] = swf[606 + jj];
#pragma unroll
        for (int kk = 0; kk < 6; kk++) {
            float ov = o[kk];
            const float4* r = (const float4*)&swf[240 + kk * 24];
#pragma unroll
            for (int qq = 0; qq < 6; qq++) {
                float4 wv = r[qq];
                hh_[qq * 4 + 0] += ov * wv.x;
                hh_[qq * 4 + 1] += ov * wv.y;
                hh_[qq * 4 + 2] += ov * wv.z;
                hh_[qq * 4 + 3] += ov * wv.w;
            }
        }
#pragma unroll
        for (int jj = 0; jj < 24; jj++) hh_[jj] = fmaxf(hh_[jj], 0.f);
        float f[6];
#pragma unroll
        for (int j = 0; j < 6; j++) f[j] = swf[630 + j];
#pragma unroll
        for (int jj = 0; jj < 24; jj++) {
            float hv = hh_[jj];
            float4 lo = *(const float4*)&swf[384 + jj * 8];
            float4 hi = *(const float4*)&swf[384 + jj * 8 + 4];
            f[0] += hv * lo.x; f[1] += hv * lo.y; f[2] += hv * lo.z; f[3] += hv * lo.w;
            f[4] += hv * hi.x; f[5] += hv * hi.y;
        }
#pragma unroll
        for (int j = 0; j < 6; j++) o[j] += f[j];
        ln6(o, swf, 636, 642);
        float wr = swf[648 + lane];
        float brepv = swf[680];
#pragma unroll
        for (int j = 0; j < 6; j++) {
            float c = o[j] * wr;
            c += __shfl_xor_sync(0xffffffffu, c, 16);
            c += __shfl_xor_sync(0xffffffffu, c, 8);
            c += __shfl_xor_sync(0xffffffffu, c, 4);
            c += __shfl_xor_sync(0xffffffffu, c, 2);
            c += __shfl_xor_sync(0xffffffffu, c, 1);
            if (lane == 0) g_feat2[(size_t)n * 70 + 64 + j] = c + brepv;
        }
    }
}

// ---------------- GAT1 aggregation: single pass, no max, deferred normalize ----------------
__global__ __launch_bounds__(256) void gat1_agg_k(const float* __restrict__ b1) {
    int gw = (blockIdx.x * blockDim.x + threadIdx.x) >> 5;
    if (gw >= NN) return;
    int lane = threadIdx.x & 31;
    int d = gw;
    int start = g_rowptr[d], deg = g_rowptr[d + 1] - start;
    int hl = lane & 7;        // head for gather lanes (4 edges x 8 heads)
    int eidx = lane >> 3;     // edge-in-chunk for gather lanes
    int c0 = lane * 2;        // output cols for this lane
    int hh = lane >> 2;       // head of output cols
    float sdd = g_s1dst[d * 8 + hl];
    float eself = __expf(leaky(sdd + g_s1src[d * 8 + hl]));
    float den = (eidx == 0) ? eself : 0.f;
    float wself = __shfl_sync(0xffffffffu, eself, hh);
    float2 xs = *(const float2*)&g_xw1[(size_t)d * 64 + c0];
    float acc0 = wself * xs.x, acc1 = wself * xs.y;
    for (int base = 0; base < deg; base += 4) {
        int e = base + eidx;
        float wv = 0.f;
        int scol = 0;
        if (e < deg) {
            scol = g_col[start + e];
            wv = __expf(leaky(sdd + g_s1src[scol * 8 + hl]));
        }
        den += wv;
#pragma unroll
        for (int i = 0; i < 4; i++) {
            if (base + i < deg) {
                int s = __shfl_sync(0xffffffffu, scol, i * 8);
                float wgt = __shfl_sync(0xffffffffu, wv, i * 8 + hh);
                float2 xv = *(const float2*)&g_xw1[(size_t)s * 64 + c0];
                acc0 += wgt * xv.x;
                acc1 += wgt * xv.y;
            }
        }
    }
    den += __shfl_xor_sync(0xffffffffu, den, 8);
    den += __shfl_xor_sync(0xffffffffu, den, 16);
    float invden = 1.f / den;                       // per lane: head hl
    float inv = __shfl_sync(0xffffffffu, invden, hh);
    float v0 = acc0 * inv + b1[c0], v1 = acc1 * inv + b1[c0 + 1];
    v0 = v0 > 0.f ? v0 : (__expf(v0) - 1.f);
    v1 = v1 > 0.f ? v1 : (__expf(v1) - 1.f);
    g_feat2[(size_t)d * 70 + c0] = v0;
    g_feat2[(size_t)d * 70 + c0 + 1] = v1;
}

// ---------------- GEMM 2 ----------------
__global__ __launch_bounds__(256) void gemm2_k(const float* __restrict__ W2) {
    __shared__ float sW[70 * 80];
    for (int i = threadIdx.x; i < 5600; i += 256) sW[i] = W2[i];
    __syncthreads();
    int lane = threadIdx.x & 31;
    int gw = (blockIdx.x * blockDim.x + threadIdx.x) >> 5;
    int nw = (gridDim.x * blockDim.x) >> 5;
    int c2 = 64 + (lane & 15);
    for (int n = gw; n < NN; n += nw) {
        const float* fr = &g_feat2[(size_t)n * 70];
        float f0 = fr[lane];
        float f1 = fr[32 + lane];
        float f2 = (lane < 6) ? fr[64 + lane] : 0.f;
        float a0 = 0.f, a1 = 0.f, a2 = 0.f;
#pragma unroll
        for (int kk = 0; kk < 32; kk++) {
            float xv = __shfl_sync(0xffffffffu, f0, kk);
            a0 += xv * sW[kk * 80 + lane];
            a1 += xv * sW[kk * 80 + 32 + lane];
            a2 += xv * sW[kk * 80 + c2];
        }
#pragma unroll
        for (int kk = 32; kk < 64; kk++) {
            float xv = __shfl_sync(0xffffffffu, f1, kk - 32);
            a0 += xv * sW[kk * 80 + lane];
            a1 += xv * sW[kk * 80 + 32 + lane];
            a2 += xv * sW[kk * 80 + c2];
        }
#pragma unroll
        for (int kk = 64; kk < 70; kk++) {
            float xv = __shfl_sync(0xffffffffu, f2, kk - 64);
            a0 += xv * sW[kk * 80 + lane];
            a1 += xv * sW[kk * 80 + 32 + lane];
            a2 += xv * sW[kk * 80 + c2];
        }
        g_xw2[(size_t)n * 80 + lane] = a0;
        g_xw2[(size_t)n * 80 + 32 + lane] = a1;
        if (lane < 16) g_xw2[(size_t)n * 80 + c2] = a2;
    }
}

// ---------------- scores for GAT2 ----------------
__global__ void scores2_k(const float* __restrict__ att2) {
    int i = blockIdx.x * blockDim.x + threadIdx.x;
    if (i >= NN * 8) return;
    int node = i >> 3, h = i & 7;
    const float* xr = g_xw2 + (size_t)node * 80 + h * 10;
    const float* ai = att2 + h * 20;
    float si = 0.f, sj = 0.f;
#pragma unroll
    for (int c = 0; c < 10; c++) { si += xr[c] * ai[c]; sj += xr[c] * ai[10 + c]; }
    g_s2dst[i] = si;
    g_s2src[i] = sj;
}

// ---------------- GAT2 aggregation (single pass) + mean heads + log_softmax ----------------
__global__ __launch_bounds__(256) void gat2_agg_k(const float* __restrict__ b2,
                                                  float* __restrict__ out) {
    __shared__ float sacc[8][80];
    __shared__ float sval[8][16];
    int gw = (blockIdx.x * blockDim.x + threadIdx.x) >> 5;
    if (gw >= NN) return;
    int lane = threadIdx.x & 31;
    int w = (threadIdx.x >> 5);
    int d = gw;
    int start = g_rowptr[d], deg = g_rowptr[d + 1] - start;
    int hl = lane & 7;
    int eidx = lane >> 3;
    float sdd = g_s2dst[d * 8 + hl];
    float eself = __expf(leaky(sdd + g_s2src[d * 8 + hl]));
    float den = (eidx == 0) ? eself : 0.f;
    int h0 = lane / 10;
    int h1 = (lane + 32) / 10;
    int h2 = (lane + 64) / 10;
    int i2 = 64 + (lane & 15);
    float ws0 = __shfl_sync(0xffffffffu, eself, h0);
    float ws1 = __shfl_sync(0xffffffffu, eself, h1);
    float ws2 = __shfl_sync(0xffffffffu, eself, h2);
    const float* xd = &g_xw2[(size_t)d * 80];
    float acc0 = ws0 * xd[lane];
    float acc1 = ws1 * xd[32 + lane];
    float acc2 = ws2 * xd[i2];
    for (int base = 0; base < deg; base += 4) {
        int e = base + eidx;
        float wv = 0.f;
        int scol = 0;
        if (e < deg) {
            scol = g_col[start + e];
            wv = __expf(leaky(sdd + g_s2src[scol * 8 + hl]));
        }
        den += wv;
#pragma unroll
        for (int i = 0; i < 4; i++) {
            if (base + i < deg) {
                int s = __shfl_sync(0xffffffffu, scol, i * 8);
                float w0 = __shfl_sync(0xffffffffu, wv, i * 8 + h0);
                float w1 = __shfl_sync(0xffffffffu, wv, i * 8 + h1);
                float w2 = __shfl_sync(0xffffffffu, wv, i * 8 + h2);
                const float* xr = &g_xw2[(size_t)s * 80];
                acc0 += w0 * xr[lane];
                acc1 += w1 * xr[32 + lane];
                acc2 += w2 * xr[i2];
            }
        }
    }
    den += __shfl_xor_sync(0xffffffffu, den, 8);
    den += __shfl_xor_sync(0xffffffffu, den, 16);
    float invden = 1.f / den;                      // per lane: head hl
    float iv0 = __shfl_sync(0xffffffffu, invden, h0);
    float iv1 = __shfl_sync(0xffffffffu, invden, h1);
    float iv2 = __shfl_sync(0xffffffffu, invden, h2);
    sacc[w][lane] = acc0 * iv0;
    sacc[w][32 + lane] = acc1 * iv1;
    if (lane < 16) sacc[w][i2] = acc2 * iv2;
    __syncwarp();
    if (lane < 10) {
        float s = 0.f;
#pragma unroll
        for (int h = 0; h < 8; h++) s += sacc[w][h * 10 + lane];
        sval[w][lane] = s * 0.125f + b2[lane];
    }
    __syncwarp();
    if (lane < 10) {
        float mx = -INFINITY;
#pragma unroll
        for (int c = 0; c < 10; c++) mx = fmaxf(mx, sval[w][c]);
        float se = 0.f;
#pragma unroll
        for (int c = 0; c < 10; c++) se += __expf(sval[w][c] - mx);
        out[(size_t)d * 10 + lane] = sval[w][lane] - mx - logf(se);
    }
}

// ---------------- launch ----------------
extern "C" void kernel_launch(void* const* d_in, const int* in_sizes, int n_in,
                              void* d_out, int out_size) {
    const float* x    = (const float*)d_in[0];
    const int*   ei   = (const int*)d_in[1];
    const float* ef   = (const float*)d_in[2];
    const float* W1   = (const float*)d_in[3];
    const float* att1 = (const float*)d_in[4];
    const float* b1   = (const float*)d_in[5];
    const float* W2   = (const float*)d_in[6];
    const float* att2 = (const float*)d_in[7];
    const float* b2   = (const float*)d_in[8];
    const float* Wq   = (const float*)d_in[9];
    const float* bq   = (const float*)d_in[10];
    const float* Wk   = (const float*)d_in[11];
    const float* bk   = (const float*)d_in[12];
    const float* Wv   = (const float*)d_in[13];
    const float* bv   = (const float*)d_in[14];
    const float* g0   = (const float*)d_in[15];
    const float* be0  = (const float*)d_in[16];
    const float* Wf1  = (const float*)d_in[17];
    const float* bf1  = (const float*)d_in[18];
    const float* Wf2  = (const float*)d_in[19];
    const float* bf2  = (const float*)d_in[20];
    const float* g1   = (const float*)d_in[21];
    const float* be1  = (const float*)d_in[22];
    const float* Wrep = (const float*)d_in[23];
    const float* brep = (const float*)d_in[24];
    float* out = (float*)d_out;
    int E = in_sizes[1] / 2;

    zero_deg_k<<<(NN + 255) / 256, 256>>>();
    hist_k<<<(E + 255) / 256, 256>>>(ei, E);
    scan1_k<<<(NN + 1023) / 1024, 256>>>();
    scan2_k<<<1, 128>>>((NN + 1023) / 1024);
    scan3_k<<<(NN + 1023) / 1024, 256>>>();
    fill_k<<<(E + 255) / 256, 256>>>(ei, E);

    gemm1_k<<<1184, 256>>>(x, W1, att1);
    encoder_k<<<1184, 256>>>(ef, Wq, bq, Wk, bk, Wv, bv, g0, be0,
                             Wf1, bf1, Wf2, bf2, g1, be1, Wrep, brep);
    gat1_agg_k<<<(NN + 7) / 8, 256>>>(b1);
    gemm2_k<<<1184, 256>>>(W2);
    scores2_k<<<(NN * 8 + 255) / 256, 256>>>(att2);
    gat2_agg_k<<<(NN + 7) / 8, 256>>>(b2, out);
}

// round 3
// speedup vs baseline: 1.1129x; 1.0000x over previous
#include <cuda_runtime.h>
#include <math.h>

#define NN 100000
#define EE 1600000

// ---------------- scratch ----------------
__device__ __align__(16) float g_xw1[NN * 64];   // x @ W1
__device__ __align__(16) float g_feat2[NN * 70]; // [h1(64) | xt(6)]
__device__ __align__(16) float g_xw2[NN * 80];   // feat2 @ W2
__device__ float g_s1src[NN * 8], g_s1dst[NN * 8];
__device__ float g_s2src[NN * 8], g_s2dst[NN * 8];
__device__ int g_deg[NN];
__device__ int g_rowptr[NN + 1];
__device__ int g_pos[NN];
__device__ int g_col[EE];
__device__ int g_bsum[128];

__device__ __forceinline__ float leaky(float a) { return a >= 0.f ? a : 0.2f * a; }

// ---------------- CSR build ----------------
__global__ void zero_deg_k() {
    int i = blockIdx.x * blockDim.x + threadIdx.x;
    if (i < NN) g_deg[i] = 0;
}

__global__ void hist_k(const int* __restrict__ ei, int E) {
    int e = blockIdx.x * blockDim.x + threadIdx.x;
    if (e >= E) return;
    int s = ei[e], d = ei[E + e];
    if (s != d) atomicAdd(&g_deg[d], 1);
}

__global__ void scan1_k() {
    int b = blockIdx.x, t = threadIdx.x;
    int base = b * 1024 + t * 4;
    int s = 0;
#pragma unroll
    for (int j = 0; j < 4; j++) {
        int i = base + j;
        if (i < NN) s += g_deg[i];
    }
    __shared__ int red[256];
    red[t] = s;
    __syncthreads();
    for (int o = 128; o > 0; o >>= 1) {
        if (t < o) red[t] += red[t + o];
        __syncthreads();
    }
    if (t == 0) g_bsum[b] = red[0];
}

__global__ void scan2_k(int nb) {
    __shared__ int s[128];
    int t = threadIdx.x;
    s[t] = (t < nb) ? g_bsum[t] : 0;
    __syncthreads();
    if (t == 0) {
        int run = 0;
        for (int i = 0; i < nb; i++) { int v = s[i]; s[i] = run; run += v; }
        g_rowptr[NN] = run;
    }
    __syncthreads();
    if (t < nb) g_bsum[t] = s[t];
}

__global__ void scan3_k() {
    int b = blockIdx.x, t = threadIdx.x;
    int base = b * 1024 + t * 4;
    int v[4];
    int tot = 0;
#pragma unroll
    for (int j = 0; j < 4; j++) {
        int i = base + j;
        v[j] = (i < NN) ? g_deg[i] : 0;
        tot += v[j];
    }
    __shared__ int sc[256];
    sc[t] = tot;
    __syncthreads();
    for (int o = 1; o < 256; o <<= 1) {
        int x = (t >= o) ? sc[t - o] : 0;
        __syncthreads();
        sc[t] += x;
        __syncthreads();
    }
    int excl = sc[t] - tot + g_bsum[b];
#pragma unroll
    for (int j = 0; j < 4; j++) {
        int i = base + j;
        if (i < NN) { g_rowptr[i] = excl; g_pos[i] = excl; excl += v[j]; }
    }
}

__global__ void fill_k(const int* __restrict__ ei, int E) {
    int e = blockIdx.x * blockDim.x + threadIdx.x;
    if (e >= E) return;
    int s = ei[e], d = ei[E + e];
    if (s != d) {
        int slot = atomicAdd(&g_pos[d], 1);
        g_col[slot] = s;
    }
}

// ---------------- GEMM 1 + fused GAT1 attention scores ----------------
__global__ __launch_bounds__(256) void gemm1_k(const float* __restrict__ x,
                                               const float* __restrict__ W1,
                                               const float* __restrict__ att1) {
    __shared__ __align__(16) float sW[64 * 64];
    __shared__ float sAtt[128];
    for (int i = threadIdx.x; i < 4096; i += 256) sW[i] = W1[i];
    if (threadIdx.x < 128) sAtt[threadIdx.x] = att1[threadIdx.x];
    __syncthreads();
    int lane = threadIdx.x & 31;
    int gw = (blockIdx.x * blockDim.x + threadIdx.x) >> 5;
    int nw = (gridDim.x * blockDim.x) >> 5;
    int h = lane >> 2;          // head for this lane's 2 cols
    int cc = (lane & 3) * 2;    // col within head
    float ai0 = sAtt[h * 16 + cc],     ai1 = sAtt[h * 16 + cc + 1];
    float aj0 = sAtt[h * 16 + 8 + cc], aj1 = sAtt[h * 16 + 8 + cc + 1];
    for (int n = gw; n < NN; n += nw) {
        float2 xr = *(const float2*)&x[n * 64 + lane * 2];
        float a0 = 0.f, a1 = 0.f;
#pragma unroll
        for (int k2 = 0; k2 < 32; k2++) {
            float xa = __shfl_sync(0xffffffffu, xr.x, k2);
            float xb = __shfl_sync(0xffffffffu, xr.y, k2);
            float2 w0 = *(const float2*)&sW[(2 * k2) * 64 + lane * 2];
            a0 += xa * w0.x; a1 += xa * w0.y;
            float2 w1 = *(const float2*)&sW[(2 * k2 + 1) * 64 + lane * 2];
            a0 += xb * w1.x; a1 += xb * w1.y;
        }
        *(float2*)&g_xw1[n * 64 + lane * 2] = make_float2(a0, a1);
        float si = a0 * ai0 + a1 * ai1;
        float sj = a0 * aj0 + a1 * aj1;
        si += __shfl_xor_sync(0xffffffffu, si, 1);
        si += __shfl_xor_sync(0xffffffffu, si, 2);
        sj += __shfl_xor_sync(0xffffffffu, sj, 1);
        sj += __shfl_xor_sync(0xffffffffu, sj, 2);
        if ((lane & 3) == 0) {
            g_s1dst[n * 8 + h] = si;
            g_s1src[n * 8 + h] = sj;
        }
    }
}

// ---------------- Encoder: warp per node ----------------
__device__ __forceinline__ void ln6(float* o, const float* swf, int goff, int boff) {
    float mu = (o[0] + o[1] + o[2] + o[3] + o[4] + o[5]) * (1.f / 6.f);
    float d0 = o[0] - mu, d1 = o[1] - mu, d2 = o[2] - mu, d3 = o[3] - mu, d4 = o[4] - mu, d5 = o[5] - mu;
    float var = (d0 * d0 + d1 * d1 + d2 * d2 + d3 * d3 + d4 * d4 + d5 * d5) * (1.f / 6.f);
    float rs = rsqrtf(var + 1e-5f);
    o[0] = d0 * rs * swf[goff + 0] + swf[boff + 0];
    o[1] = d1 * rs * swf[goff + 1] + swf[boff + 1];
    o[2] = d2 * rs * swf[goff + 2] + swf[boff + 2];
    o[3] = d3 * rs * swf[goff + 3] + swf[boff + 3];
    o[4] = d4 * rs * swf[goff + 4] + swf[boff + 4];
    o[5] = d5 * rs * swf[goff + 5] + swf[boff + 5];
}

__global__ __launch_bounds__(256) void encoder_k(
    const float* __restrict__ ef,
    const float* __restrict__ Wq, const float* __restrict__ bq,
    const float* __restrict__ Wk, const float* __restrict__ bk,
    const float* __restrict__ Wv, const float* __restrict__ bv,
    const float* __restrict__ g0, const float* __restrict__ be0,
    const float* __restrict__ Wf1, const float* __restrict__ bf1,
    const float* __restrict__ Wf2, const float* __restrict__ bf2,
    const float* __restrict__ g1, const float* __restrict__ be1,
    const float* __restrict__ Wrep, const float* __restrict__ brep) {
    __shared__ __align__(16) float swf[688];
    __shared__ float4 sK[8][32][2];
    __shared__ float4 sV[8][32][2];
    int tid = threadIdx.x;
    for (int i = tid; i < 688; i += 256) swf[i] = 0.f;
    __syncthreads();
    for (int i = tid; i < 60; i += 256) {
        int kk = i / 6, j = i % 6;
        swf[kk * 8 + j] = Wq[i];
        swf[80 + kk * 8 + j] = Wk[i];
        swf[160 + kk * 8 + j] = Wv[i];
    }
    for (int i = tid; i < 144; i += 256) swf[240 + i] = Wf1[i];
    for (int i = tid; i < 144; i += 256) swf[384 + (i / 6) * 8 + (i % 6)] = Wf2[i];
    if (tid < 6) {
        swf[576 + tid] = bq[tid]; swf[582 + tid] = bk[tid]; swf[588 + tid] = bv[tid];
        swf[594 + tid] = g0[tid]; swf[600 + tid] = be0[tid]; swf[630 + tid] = bf2[tid];
        swf[636 + tid] = g1[tid]; swf[642 + tid] = be1[tid];
    }
    if (tid < 24) swf[606 + tid] = bf1[tid];
    if (tid < 32) swf[648 + tid] = Wrep[tid];
    if (tid == 0) swf[680] = brep[0];
    __syncthreads();

    int lane = tid & 31, w = tid >> 5;
    int gw = (blockIdx.x * blockDim.x + tid) >> 5;
    int nwarps = (gridDim.x * blockDim.x) >> 5;
    const float SCALE = 0.40824829046386307f; // 1/sqrt(6)

    for (int n = gw; n < NN; n += nwarps) {
        const float* xr = ef + (size_t)n * 320 + lane * 10;
        float2 p0 = *(const float2*)xr, p1 = *(const float2*)(xr + 2),
               p2 = *(const float2*)(xr + 4), p3 = *(const float2*)(xr + 6),
               p4 = *(const float2*)(xr + 8);
        float xa[10] = {p0.x, p0.y, p1.x, p1.y, p2.x, p2.y, p3.x, p3.y, p4.x, p4.y};
        float q[6], k[6], v[6];
#pragma unroll
        for (int j = 0; j < 6; j++) { q[j] = swf[576 + j]; k[j] = swf[582 + j]; v[j] = swf[588 + j]; }
#pragma unroll
        for (int kk = 0; kk < 10; kk++) {
            float xv = xa[kk];
            float4 a = *(const float4*)&swf[kk * 8], b4 = *(const float4*)&swf[kk * 8 + 4];
            q[0] += xv * a.x; q[1] += xv * a.y; q[2] += xv * a.z; q[3] += xv * a.w;
            q[4] += xv * b4.x; q[5] += xv * b4.y;
            float4 c = *(const float4*)&swf[80 + kk * 8], d4 = *(const float4*)&swf[80 + kk * 8 + 4];
            k[0] += xv * c.x; k[1] += xv * c.y; k[2] += xv * c.z; k[3] += xv * c.w;
            k[4] += xv * d4.x; k[5] += xv * d4.y;
            float4 e4 = *(const float4*)&swf[160 + kk * 8], f4 = *(const float4*)&swf[160 + kk * 8 + 4];
            v[0] += xv * e4.x; v[1] += xv * e4.y; v[2] += xv * e4.z; v[3] += xv * e4.w;
            v[4] += xv * f4.x; v[5] += xv * f4.y;
        }
        sK[w][lane][0] = make_float4(k[0], k[1], k[2], 0.f);
        sK[w][lane][1] = make_float4(k[3], k[4], k[5], 0.f);
        sV[w][lane][0] = make_float4(v[0], v[1], v[2], 0.f);
        sV[w][lane][1] = make_float4(v[3], v[4], v[5], 0.f);
        __syncwarp();
        float o[6];
#pragma unroll
        for (int h = 0; h < 2; h++) {
            float q0 = q[h * 3], q1 = q[h * 3 + 1], q2 = q[h * 3 + 2];
            // logits are O(1): plain exp-sum softmax, no running max needed
            float l = 0.f, a0 = 0.f, a1 = 0.f, a2 = 0.f;
#pragma unroll
            for (int tp = 0; tp < 32; tp++) {
                float4 kk4 = sK[w][tp][h];
                float s = (q0 * kk4.x + q1 * kk4.y + q2 * kk4.z) * SCALE;
                float p = __expf(s);
                float4 vv = sV[w][tp][h];
                l += p;
                a0 += p * vv.x;
                a1 += p * vv.y;
                a2 += p * vv.z;
            }
            float inv = 1.f / l;
            o[h * 3 + 0] = q0 + a0 * inv;
            o[h * 3 + 1] = q1 + a1 * inv;
            o[h * 3 + 2] = q2 + a2 * inv;
        }
        __syncwarp();
        ln6(o, swf, 594, 600);
        float hh_[24];
#pragma unroll
        for (int jj = 0; jj < 24; jj++) hh_[jj] = swf[606 + jj];
#pragma unroll
        for (int kk = 0; kk < 6; kk++) {
            float ov = o[kk];
            const float4* r = (const float4*)&swf[240 + kk * 24];
#pragma unroll
            for (int qq = 0; qq < 6; qq++) {
                float4 wv = r[qq];
                hh_[qq * 4 + 0] += ov * wv.x;
                hh_[qq * 4 + 1] += ov * wv.y;
                hh_[qq * 4 + 2] += ov * wv.z;
                hh_[qq * 4 + 3] += ov * wv.w;
            }
        }
#pragma unroll
        for (int jj = 0; jj < 24; jj++) hh_[jj] = fmaxf(hh_[jj], 0.f);
        float f[6];
#pragma unroll
        for (int j = 0; j < 6; j++) f[j] = swf[630 + j];
#pragma unroll
        for (int jj = 0; jj < 24; jj++) {
            float hv = hh_[jj];
            float4 lo = *(const float4*)&swf[384 + jj * 8];
            float4 hi = *(const float4*)&swf[384 + jj * 8 + 4];
            f[0] += hv * lo.x; f[1] += hv * lo.y; f[2] += hv * lo.z; f[3] += hv * lo.w;
            f[4] += hv * hi.x; f[5] += hv * hi.y;
        }
#pragma unroll
        for (int j = 0; j < 6; j++) o[j] += f[j];
        ln6(o, swf, 636, 642);
        float wr = swf[648 + lane];
        float brepv = swf[680];
#pragma unroll
        for (int j = 0; j < 6; j++) {
            float c = o[j] * wr;
            c += __shfl_xor_sync(0xffffffffu, c, 16);
            c += __shfl_xor_sync(0xffffffffu, c, 8);
            c += __shfl_xor_sync(0xffffffffu, c, 4);
            c += __shfl_xor_sync(0xffffffffu, c, 2);
            c += __shfl_xor_sync(0xffffffffu, c, 1);
            if (lane == 0) g_feat2[(size_t)n * 70 + 64 + j] = c + brepv;
        }
    }
}

// ---------------- GAT1 aggregation: single pass, no max, deferred normalize ----------------
__global__ __launch_bounds__(256) void gat1_agg_k(const float* __restrict__ b1) {
    int gw = (blockIdx.x * blockDim.x + threadIdx.x) >> 5;
    if (gw >= NN) return;
    int lane = threadIdx.x & 31;
    int d = gw;
    int start = g_rowptr[d], deg = g_rowptr[d + 1] - start;
    int hl = lane & 7;        // head for gather lanes (4 edges x 8 heads)
    int eidx = lane >> 3;     // edge-in-chunk for gather lanes
    int c0 = lane * 2;        // output cols for this lane
    int hh = lane >> 2;       // head of output cols
    float sdd = g_s1dst[d * 8 + hl];
    float eself = __expf(leaky(sdd + g_s1src[d * 8 + hl]));
    float den = (eidx == 0) ? eself : 0.f;
    float wself = __shfl_sync(0xffffffffu, eself, hh);
    float2 xs = *(const float2*)&g_xw1[(size_t)d * 64 + c0];
    float acc0 = wself * xs.x, acc1 = wself * xs.y;
    for (int base = 0; base < deg; base += 4) {
        int e = base + eidx;
        float wv = 0.f;
        int scol = 0;
        if (e < deg) {
            scol = g_col[start + e];
            wv = __expf(leaky(sdd + g_s1src[scol * 8 + hl]));
        }
        den += wv;
#pragma unroll
        for (int i = 0; i < 4; i++) {
            if (base + i < deg) {
                int s = __shfl_sync(0xffffffffu, scol, i * 8);
                float wgt = __shfl_sync(0xffffffffu, wv, i * 8 + hh);
                float2 xv = *(const float2*)&g_xw1[(size_t)s * 64 + c0];
                acc0 += wgt * xv.x;
                acc1 += wgt * xv.y;
            }
        }
    }
    den += __shfl_xor_sync(0xffffffffu, den, 8);
    den += __shfl_xor_sync(0xffffffffu, den, 16);
    float invden = 1.f / den;                       // per lane: head hl
    float inv = __shfl_sync(0xffffffffu, invden, hh);
    float v0 = acc0 * inv + b1[c0], v1 = acc1 * inv + b1[c0 + 1];
    v0 = v0 > 0.f ? v0 : (__expf(v0) - 1.f);
    v1 = v1 > 0.f ? v1 : (__expf(v1) - 1.f);
    g_feat2[(size_t)d * 70 + c0] = v0;
    g_feat2[(size_t)d * 70 + c0 + 1] = v1;
}

// ---------------- GEMM 2 ----------------
__global__ __launch_bounds__(256) void gemm2_k(const float* __restrict__ W2) {
    __shared__ float sW[70 * 80];
    for (int i = threadIdx.x; i < 5600; i += 256) sW[i] = W2[i];
    __syncthreads();
    int lane = threadIdx.x & 31;
    int gw = (blockIdx.x * blockDim.x + threadIdx.x) >> 5;
    int nw = (gridDim.x * blockDim.x) >> 5;
    int c2 = 64 + (lane & 15);
    for (int n = gw; n < NN; n += nw) {
        const float* fr = &g_feat2[(size_t)n * 70];
        float f0 = fr[lane];
        float f1 = fr[32 + lane];
        float f2 = (lane < 6) ? fr[64 + lane] : 0.f;
        float a0 = 0.f, a1 = 0.f, a2 = 0.f;
#pragma unroll
        for (int kk = 0; kk < 32; kk++) {
            float xv = __shfl_sync(0xffffffffu, f0, kk);
            a0 += xv * sW[kk * 80 + lane];
            a1 += xv * sW[kk * 80 + 32 + lane];
            a2 += xv * sW[kk * 80 + c2];
        }
#pragma unroll
        for (int kk = 32; kk < 64; kk++) {
            float xv = __shfl_sync(0xffffffffu, f1, kk - 32);
            a0 += xv * sW[kk * 80 + lane];
            a1 += xv * sW[kk * 80 + 32 + lane];
            a2 += xv * sW[kk * 80 + c2];
        }
#pragma unroll
        for (int kk = 64; kk < 70; kk++) {
            float xv = __shfl_sync(0xffffffffu, f2, kk - 64);
            a0 += xv * sW[kk * 80 + lane];
            a1 += xv * sW[kk * 80 + 32 + lane];
            a2 += xv * sW[kk * 80 + c2];
        }
        g_xw2[(size_t)n * 80 + lane] = a0;
        g_xw2[(size_t)n * 80 + 32 + lane] = a1;
        if (lane < 16) g_xw2[(size_t)n * 80 + c2] = a2;
    }
}

// ---------------- scores for GAT2 ----------------
__global__ void scores2_k(const float* __restrict__ att2) {
    int i = blockIdx.x * blockDim.x + threadIdx.x;
    if (i >= NN * 8) return;
    int node = i >> 3, h = i & 7;
    const float* xr = g_xw2 + (size_t)node * 80 + h * 10;
    const float* ai = att2 + h * 20;
    float si = 0.f, sj = 0.f;
#pragma unroll
    for (int c = 0; c < 10; c++) { si += xr[c] * ai[c]; sj += xr[c] * ai[10 + c]; }
    g_s2dst[i] = si;
    g_s2src[i] = sj;
}

// ---------------- GAT2 aggregation (single pass) + mean heads + log_softmax ----------------
__global__ __launch_bounds__(256) void gat2_agg_k(const float* __restrict__ b2,
                                                  float* __restrict__ out) {
    __shared__ float sacc[8][80];
    __shared__ float sval[8][16];
    int gw = (blockIdx.x * blockDim.x + threadIdx.x) >> 5;
    if (gw >= NN) return;
    int lane = threadIdx.x & 31;
    int w = (threadIdx.x >> 5);
    int d = gw;
    int start = g_rowptr[d], deg = g_rowptr[d + 1] - start;
    int hl = lane & 7;
    int eidx = lane >> 3;
    float sdd = g_s2dst[d * 8 + hl];
    float eself = __expf(leaky(sdd + g_s2src[d * 8 + hl]));
    float den = (eidx == 0) ? eself : 0.f;
    int h0 = lane / 10;
    int h1 = (lane + 32) / 10;
    int h2 = (lane + 64) / 10;
    int i2 = 64 + (lane & 15);
    float ws0 = __shfl_sync(0xffffffffu, eself, h0);
    float ws1 = __shfl_sync(0xffffffffu, eself, h1);
    float ws2 = __shfl_sync(0xffffffffu, eself, h2);
    const float* xd = &g_xw2[(size_t)d * 80];
    float acc0 = ws0 * xd[lane];
    float acc1 = ws1 * xd[32 + lane];
    float acc2 = ws2 * xd[i2];
    for (int base = 0; base < deg; base += 4) {
        int e = base + eidx;
        float wv = 0.f;
        int scol = 0;
        if (e < deg) {
            scol = g_col[start + e];
            wv = __expf(leaky(sdd + g_s2src[scol * 8 + hl]));
        }
        den += wv;
#pragma unroll
        for (int i = 0; i < 4; i++) {
            if (base + i < deg) {
                int s = __shfl_sync(0xffffffffu, scol, i * 8);
                float w0 = __shfl_sync(0xffffffffu, wv, i * 8 + h0);
                float w1 = __shfl_sync(0xffffffffu, wv, i * 8 + h1);
                float w2 = __shfl_sync(0xffffffffu, wv, i * 8 + h2);
                const float* xr = &g_xw2[(size_t)s * 80];
                acc0 += w0 * xr[lane];
                acc1 += w1 * xr[32 + lane];
                acc2 += w2 * xr[i2];
            }
        }
    }
    den += __shfl_xor_sync(0xffffffffu, den, 8);
    den += __shfl_xor_sync(0xffffffffu, den, 16);
    float invden = 1.f / den;                      // per lane: head hl
    float iv0 = __shfl_sync(0xffffffffu, invden, h0);
    float iv1 = __shfl_sync(0xffffffffu, invden, h1);
    float iv2 = __shfl_sync(0xffffffffu, invden, h2);
    sacc[w][lane] = acc0 * iv0;
    sacc[w][32 + lane] = acc1 * iv1;
    if (lane < 16) sacc[w][i2] = acc2 * iv2;
    __syncwarp();
    if (lane < 10) {
        float s = 0.f;
#pragma unroll
        for (int h = 0; h < 8; h++) s += sacc[w][h * 10 + lane];
        sval[w][lane] = s * 0.125f + b2[lane];
    }
    __syncwarp();
    if (lane < 10) {
        float mx = -INFINITY;
#pragma unroll
        for (int c = 0; c < 10; c++) mx = fmaxf(mx, sval[w][c]);
        float se = 0.f;
#pragma unroll
        for (int c = 0; c < 10; c++) se += __expf(sval[w][c] - mx);
        out[(size_t)d * 10 + lane] = sval[w][lane] - mx - logf(se);
    }
}

// ---------------- launch ----------------
extern "C" void kernel_launch(void* const* d_in, const int* in_sizes, int n_in,
                              void* d_out, int out_size) {
    const float* x    = (const float*)d_in[0];
    const int*   ei   = (const int*)d_in[1];
    const float* ef   = (const float*)d_in[2];
    const float* W1   = (const float*)d_in[3];
    const float* att1 = (const float*)d_in[4];
    const float* b1   = (const float*)d_in[5];
    const float* W2   = (const float*)d_in[6];
    const float* att2 = (const float*)d_in[7];
    const float* b2   = (const float*)d_in[8];
    const float* Wq   = (const float*)d_in[9];
    const float* bq   = (const float*)d_in[10];
    const float* Wk   = (const float*)d_in[11];
    const float* bk   = (const float*)d_in[12];
    const float* Wv   = (const float*)d_in[13];
    const float* bv   = (const float*)d_in[14];
    const float* g0   = (const float*)d_in[15];
    const float* be0  = (const float*)d_in[16];
    const float* Wf1  = (const float*)d_in[17];
    const float* bf1  = (const float*)d_in[18];
    const float* Wf2  = (const float*)d_in[19];
    const float* bf2  = (const float*)d_in[20];
    const float* g1   = (const float*)d_in[21];
    const float* be1  = (const float*)d_in[22];
    const float* Wrep = (const float*)d_in[23];
    const float* brep = (const float*)d_in[24];
    float* out = (float*)d_out;
    int E = in_sizes[1] / 2;

    zero_deg_k<<<(NN + 255) / 256, 256>>>();
    hist_k<<<(E + 255) / 256, 256>>>(ei, E);
    scan1_k<<<(NN + 1023) / 1024, 256>>>();
    scan2_k<<<1, 128>>>((NN + 1023) / 1024);
    scan3_k<<<(NN + 1023) / 1024, 256>>>();
    fill_k<<<(E + 255) / 256, 256>>>(ei, E);

    gemm1_k<<<1184, 256>>>(x, W1, att1);
    encoder_k<<<1184, 256>>>(ef, Wq, bq, Wk, bk, Wv, bv, g0, be0,
                             Wf1, bf1, Wf2, bf2, g1, be1, Wrep, brep);
    gat1_agg_k<<<(NN + 7) / 8, 256>>>(b1);
    gemm2_k<<<1184, 256>>>(W2);
    scores2_k<<<(NN * 8 + 255) / 256, 256>>>(att2);
    gat2_agg_k<<<(NN + 7) / 8, 256>>>(b2, out);
}

// round 4
// speedup vs baseline: 1.1154x; 1.0023x over previous
#include <cuda_runtime.h>
#include <math.h>

#define NN 100000
#define EE 1600000

// ---------------- scratch ----------------
__device__ __align__(16) float g_xw1[NN * 64];   // x @ W1
__device__ __align__(16) float g_feat2[NN * 70]; // [h1(64) | xt(6)]
__device__ __align__(16) float g_xw2[NN * 80];   // feat2 @ W2
__device__ float g_s1src[NN * 8], g_s1dst[NN * 8];
__device__ float g_s2src[NN * 8], g_s2dst[NN * 8];
__device__ int g_deg[NN];
__device__ int g_rowptr[NN + 1];
__device__ int g_pos[NN];
__device__ int g_col[EE];
__device__ int g_bsum[128];

__device__ __forceinline__ float leaky(float a) { return a >= 0.f ? a : 0.2f * a; }

// ---------------- CSR build ----------------
__global__ void zero_deg_k() {
    int i = blockIdx.x * blockDim.x + threadIdx.x;
    if (i < NN) g_deg[i] = 0;
}

__global__ void hist_k(const int* __restrict__ ei, int E) {
    int e = blockIdx.x * blockDim.x + threadIdx.x;
    if (e >= E) return;
    int s = ei[e], d = ei[E + e];
    if (s != d) atomicAdd(&g_deg[d], 1);
}

__global__ void scan1_k() {
    int b = blockIdx.x, t = threadIdx.x;
    int base = b * 1024 + t * 4;
    int s = 0;
#pragma unroll
    for (int j = 0; j < 4; j++) {
        int i = base + j;
        if (i < NN) s += g_deg[i];
    }
    __shared__ int red[256];
    red[t] = s;
    __syncthreads();
    for (int o = 128; o > 0; o >>= 1) {
        if (t < o) red[t] += red[t + o];
        __syncthreads();
    }
    if (t == 0) g_bsum[b] = red[0];
}

__global__ void scan2_k(int nb) {
    __shared__ int s[128];
    int t = threadIdx.x;
    s[t] = (t < nb) ? g_bsum[t] : 0;
    __syncthreads();
    if (t == 0) {
        int run = 0;
        for (int i = 0; i < nb; i++) { int v = s[i]; s[i] = run; run += v; }
        g_rowptr[NN] = run;
    }
    __syncthreads();
    if (t < nb) g_bsum[t] = s[t];
}

__global__ void scan3_k() {
    int b = blockIdx.x, t = threadIdx.x;
    int base = b * 1024 + t * 4;
    int v[4];
    int tot = 0;
#pragma unroll
    for (int j = 0; j < 4; j++) {
        int i = base + j;
        v[j] = (i < NN) ? g_deg[i] : 0;
        tot += v[j];
    }
    __shared__ int sc[256];
    sc[t] = tot;
    __syncthreads();
    for (int o = 1; o < 256; o <<= 1) {
        int x = (t >= o) ? sc[t - o] : 0;
        __syncthreads();
        sc[t] += x;
        __syncthreads();
    }
    int excl = sc[t] - tot + g_bsum[b];
#pragma unroll
    for (int j = 0; j < 4; j++) {
        int i = base + j;
        if (i < NN) { g_rowptr[i] = excl; g_pos[i] = excl; excl += v[j]; }
    }
}

__global__ void fill_k(const int* __restrict__ ei, int E) {
    int e = blockIdx.x * blockDim.x + threadIdx.x;
    if (e >= E) return;
    int s = ei[e], d = ei[E + e];
    if (s != d) {
        int slot = atomicAdd(&g_pos[d], 1);
        g_col[slot] = s;
    }
}

// ---------------- GEMM 1 + fused GAT1 attention scores ----------------
__global__ __launch_bounds__(256) void gemm1_k(const float* __restrict__ x,
                                               const float* __restrict__ W1,
                                               const float* __restrict__ att1) {
    __shared__ __align__(16) float sW[64 * 64];
    __shared__ float sAtt[128];
    for (int i = threadIdx.x; i < 4096; i += 256) sW[i] = W1[i];
    if (threadIdx.x < 128) sAtt[threadIdx.x] = att1[threadIdx.x];
    __syncthreads();
    int lane = threadIdx.x & 31;
    int gw = (blockIdx.x * blockDim.x + threadIdx.x) >> 5;
    int nw = (gridDim.x * blockDim.x) >> 5;
    int h = lane >> 2;          // head for this lane's 2 cols
    int cc = (lane & 3) * 2;    // col within head
    float ai0 = sAtt[h * 16 + cc],     ai1 = sAtt[h * 16 + cc + 1];
    float aj0 = sAtt[h * 16 + 8 + cc], aj1 = sAtt[h * 16 + 8 + cc + 1];
    for (int n = gw; n < NN; n += nw) {
        float2 xr = *(const float2*)&x[n * 64 + lane * 2];
        float a0 = 0.f, a1 = 0.f;
#pragma unroll
        for (int k2 = 0; k2 < 32; k2++) {
            float xa = __shfl_sync(0xffffffffu, xr.x, k2);
            float xb = __shfl_sync(0xffffffffu, xr.y, k2);
            float2 w0 = *(const float2*)&sW[(2 * k2) * 64 + lane * 2];
            a0 += xa * w0.x; a1 += xa * w0.y;
            float2 w1 = *(const float2*)&sW[(2 * k2 + 1) * 64 + lane * 2];
            a0 += xb * w1.x; a1 += xb * w1.y;
        }
        *(float2*)&g_xw1[n * 64 + lane * 2] = make_float2(a0, a1);
        float si = a0 * ai0 + a1 * ai1;
        float sj = a0 * aj0 + a1 * aj1;
        si += __shfl_xor_sync(0xffffffffu, si, 1);
        si += __shfl_xor_sync(0xffffffffu, si, 2);
        sj += __shfl_xor_sync(0xffffffffu, sj, 1);
        sj += __shfl_xor_sync(0xffffffffu, sj, 2);
        if ((lane & 3) == 0) {
            g_s1dst[n * 8 + h] = si;
            g_s1src[n * 8 + h] = sj;
        }
    }
}

// ---------------- Encoder: warp per node ----------------
__device__ __forceinline__ void ln6(float* o, const float* swf, int goff, int boff) {
    float mu = (o[0] + o[1] + o[2] + o[3] + o[4] + o[5]) * (1.f / 6.f);
    float d0 = o[0] - mu, d1 = o[1] - mu, d2 = o[2] - mu, d3 = o[3] - mu, d4 = o[4] - mu, d5 = o[5] - mu;
    float var = (d0 * d0 + d1 * d1 + d2 * d2 + d3 * d3 + d4 * d4 + d5 * d5) * (1.f / 6.f);
    float rs = rsqrtf(var + 1e-5f);
    o[0] = d0 * rs * swf[goff + 0] + swf[boff + 0];
    o[1] = d1 * rs * swf[goff + 1] + swf[boff + 1];
    o[2] = d2 * rs * swf[goff + 2] + swf[boff + 2];
    o[3] = d3 * rs * swf[goff + 3] + swf[boff + 3];
    o[4] = d4 * rs * swf[goff + 4] + swf[boff + 4];
    o[5] = d5 * rs * swf[goff + 5] + swf[boff + 5];
}

__global__ __launch_bounds__(256) void encoder_k(
    const float* __restrict__ ef,
    const float* __restrict__ Wq, const float* __restrict__ bq,
    const float* __restrict__ Wk, const float* __restrict__ bk,
    const float* __restrict__ Wv, const float* __restrict__ bv,
    const float* __restrict__ g0, const float* __restrict__ be0,
    const float* __restrict__ Wf1, const float* __restrict__ bf1,
    const float* __restrict__ Wf2, const float* __restrict__ bf2,
    const float* __restrict__ g1, const float* __restrict__ be1,
    const float* __restrict__ Wrep, const float* __restrict__ brep) {
    __shared__ __align__(16) float swf[688];
    __shared__ float4 sK[8][32][2];
    __shared__ float4 sV[8][32][2];
    int tid = threadIdx.x;
    for (int i = tid; i < 688; i += 256) swf[i] = 0.f;
    __syncthreads();
    for (int i = tid; i < 60; i += 256) {
        int kk = i / 6, j = i % 6;
        swf[kk * 8 + j] = Wq[i];
        swf[80 + kk * 8 + j] = Wk[i];
        swf[160 + kk * 8 + j] = Wv[i];
    }
    for (int i = tid; i < 144; i += 256) swf[240 + i] = Wf1[i];
    for (int i = tid; i < 144; i += 256) swf[384 + (i / 6) * 8 + (i % 6)] = Wf2[i];
    if (tid < 6) {
        swf[576 + tid] = bq[tid]; swf[582 + tid] = bk[tid]; swf[588 + tid] = bv[tid];
        swf[594 + tid] = g0[tid]; swf[600 + tid] = be0[tid]; swf[630 + tid] = bf2[tid];
        swf[636 + tid] = g1[tid]; swf[642 + tid] = be1[tid];
    }
    if (tid < 24) swf[606 + tid] = bf1[tid];
    if (tid < 32) swf[648 + tid] = Wrep[tid];
    if (tid == 0) swf[680] = brep[0];
    __syncthreads();

    int lane = tid & 31, w = tid >> 5;
    int gw = (blockIdx.x * blockDim.x + tid) >> 5;
    int nwarps = (gridDim.x * blockDim.x) >> 5;
    const float SCALE = 0.40824829046386307f; // 1/sqrt(6)

    for (int n = gw; n < NN; n += nwarps) {
        const float* xr = ef + (size_t)n * 320 + lane * 10;
        float2 p0 = *(const float2*)xr, p1 = *(const float2*)(xr + 2),
               p2 = *(const float2*)(xr + 4), p3 = *(const float2*)(xr + 6),
               p4 = *(const float2*)(xr + 8);
        float xa[10] = {p0.x, p0.y, p1.x, p1.y, p2.x, p2.y, p3.x, p3.y, p4.x, p4.y};
        float q[6], k[6], v[6];
#pragma unroll
        for (int j = 0; j < 6; j++) { q[j] = swf[576 + j]; k[j] = swf[582 + j]; v[j] = swf[588 + j]; }
#pragma unroll
        for (int kk = 0; kk < 10; kk++) {
            float xv = xa[kk];
            float4 a = *(const float4*)&swf[kk * 8], b4 = *(const float4*)&swf[kk * 8 + 4];
            q[0] += xv * a.x; q[1] += xv * a.y; q[2] += xv * a.z; q[3] += xv * a.w;
            q[4] += xv * b4.x; q[5] += xv * b4.y;
            float4 c = *(const float4*)&swf[80 + kk * 8], d4 = *(const float4*)&swf[80 + kk * 8 + 4];
            k[0] += xv * c.x; k[1] += xv * c.y; k[2] += xv * c.z; k[3] += xv * c.w;
            k[4] += xv * d4.x; k[5] += xv * d4.y;
            float4 e4 = *(const float4*)&swf[160 + kk * 8], f4 = *(const float4*)&swf[160 + kk * 8 + 4];
            v[0] += xv * e4.x; v[1] += xv * e4.y; v[2] += xv * e4.z; v[3] += xv * e4.w;
            v[4] += xv * f4.x; v[5] += xv * f4.y;
        }
        sK[w][lane][0] = make_float4(k[0], k[1], k[2], 0.f);
        sK[w][lane][1] = make_float4(k[3], k[4], k[5], 0.f);
        sV[w][lane][0] = make_float4(v[0], v[1], v[2], 0.f);
        sV[w][lane][1] = make_float4(v[3], v[4], v[5], 0.f);
        __syncwarp();
        float o[6];
#pragma unroll
        for (int h = 0; h < 2; h++) {
            float q0 = q[h * 3], q1 = q[h * 3 + 1], q2 = q[h * 3 + 2];
            // logits are O(1): plain exp-sum softmax, no running max needed
            float l = 0.f, a0 = 0.f, a1 = 0.f, a2 = 0.f;
#pragma unroll
            for (int tp = 0; tp < 32; tp++) {
                float4 kk4 = sK[w][tp][h];
                float s = (q0 * kk4.x + q1 * kk4.y + q2 * kk4.z) * SCALE;
                float p = __expf(s);
                float4 vv = sV[w][tp][h];
                l += p;
                a0 += p * vv.x;
                a1 += p * vv.y;
                a2 += p * vv.z;
            }
            float inv = 1.f / l;
            o[h * 3 + 0] = q0 + a0 * inv;
            o[h * 3 + 1] = q1 + a1 * inv;
            o[h * 3 + 2] = q2 + a2 * inv;
        }
        __syncwarp();
        ln6(o, swf, 594, 600);
        float hh_[24];
#pragma unroll
        for (int jj = 0; jj < 24; jj++) hh_[jj] = swf[606 + jj];
#pragma unroll
        for (int kk = 0; kk < 6; kk++) {
            float ov = o[kk];
            const float4* r = (const float4*)&swf[240 + kk * 24];
#pragma unroll
            for (int qq = 0; qq < 6; qq++) {
                float4 wv = r[qq];
                hh_[qq * 4 + 0] += ov * wv.x;
                hh_[qq * 4 + 1] += ov * wv.y;
                hh_[qq * 4 + 2] += ov * wv.z;
                hh_[qq * 4 + 3] += ov * wv.w;
            }
        }
#pragma unroll
        for (int jj = 0; jj < 24; jj++) hh_[jj] = fmaxf(hh_[jj], 0.f);
        float f[6];
#pragma unroll
        for (int j = 0; j < 6; j++) f[j] = swf[630 + j];
#pragma unroll
        for (int jj = 0; jj < 24; jj++) {
            float hv = hh_[jj];
            float4 lo = *(const float4*)&swf[384 + jj * 8];
            float4 hi = *(const float4*)&swf[384 + jj * 8 + 4];
            f[0] += hv * lo.x; f[1] += hv * lo.y; f[2] += hv * lo.z; f[3] += hv * lo.w;
            f[4] += hv * hi.x; f[5] += hv * hi.y;
        }
#pragma unroll
        for (int j = 0; j < 6; j++) o[j] += f[j];
        ln6(o, swf, 636, 642);
        float wr = swf[648 + lane];
        float brepv = swf[680];
#pragma unroll
        for (int j = 0; j < 6; j++) {
            float c = o[j] * wr;
            c += __shfl_xor_sync(0xffffffffu, c, 16);
            c += __shfl_xor_sync(0xffffffffu, c, 8);
            c += __shfl_xor_sync(0xffffffffu, c, 4);
            c += __shfl_xor_sync(0xffffffffu, c, 2);
            c += __shfl_xor_sync(0xffffffffu, c, 1);
            if (lane == 0) g_feat2[(size_t)n * 70 + 64 + j] = c + brepv;
        }
    }
}

// ---------------- GAT1 aggregation: single pass, no max, deferred normalize ----------------
__global__ __launch_bounds__(256) void gat1_agg_k(const float* __restrict__ b1) {
    int gw = (blockIdx.x * blockDim.x + threadIdx.x) >> 5;
    if (gw >= NN) return;
    int lane = threadIdx.x & 31;
    int d = gw;
    int start = g_rowptr[d], deg = g_rowptr[d + 1] - start;
    int hl = lane & 7;        // head for gather lanes (4 edges x 8 heads)
    int eidx = lane >> 3;     // edge-in-chunk for gather lanes
    int c0 = lane * 2;        // output cols for this lane
    int hh = lane >> 2;       // head of output cols
    float sdd = g_s1dst[d * 8 + hl];
    float eself = __expf(leaky(sdd + g_s1src[d * 8 + hl]));
    float den = (eidx == 0) ? eself : 0.f;
    float wself = __shfl_sync(0xffffffffu, eself, hh);
    float2 xs = *(const float2*)&g_xw1[(size_t)d * 64 + c0];
    float acc0 = wself * xs.x, acc1 = wself * xs.y;
    for (int base = 0; base < deg; base += 4) {
        int e = base + eidx;
        float wv = 0.f;
        int scol = 0;
        if (e < deg) {
            scol = g_col[start + e];
            wv = __expf(leaky(sdd + g_s1src[scol * 8 + hl]));
        }
        den += wv;
#pragma unroll
        for (int i = 0; i < 4; i++) {
            if (base + i < deg) {
                int s = __shfl_sync(0xffffffffu, scol, i * 8);
                float wgt = __shfl_sync(0xffffffffu, wv, i * 8 + hh);
                float2 xv = *(const float2*)&g_xw1[(size_t)s * 64 + c0];
                acc0 += wgt * xv.x;
                acc1 += wgt * xv.y;
            }
        }
    }
    den += __shfl_xor_sync(0xffffffffu, den, 8);
    den += __shfl_xor_sync(0xffffffffu, den, 16);
    float invden = 1.f / den;                       // per lane: head hl
    float inv = __shfl_sync(0xffffffffu, invden, hh);
    float v0 = acc0 * inv + b1[c0], v1 = acc1 * inv + b1[c0 + 1];
    v0 = v0 > 0.f ? v0 : (__expf(v0) - 1.f);
    v1 = v1 > 0.f ? v1 : (__expf(v1) - 1.f);
    g_feat2[(size_t)d * 70 + c0] = v0;
    g_feat2[(size_t)d * 70 + c0 + 1] = v1;
}

// ---------------- GEMM 2 ----------------
__global__ __launch_bounds__(256) void gemm2_k(const float* __restrict__ W2) {
    __shared__ float sW[70 * 80];
    for (int i = threadIdx.x; i < 5600; i += 256) sW[i] = W2[i];
    __syncthreads();
    int lane = threadIdx.x & 31;
    int gw = (blockIdx.x * blockDim.x + threadIdx.x) >> 5;
    int nw = (gridDim.x * blockDim.x) >> 5;
    int c2 = 64 + (lane & 15);
    for (int n = gw; n < NN; n += nw) {
        const float* fr = &g_feat2[(size_t)n * 70];
        float f0 = fr[lane];
        float f1 = fr[32 + lane];
        float f2 = (lane < 6) ? fr[64 + lane] : 0.f;
        float a0 = 0.f, a1 = 0.f, a2 = 0.f;
#pragma unroll
        for (int kk = 0; kk < 32; kk++) {
            float xv = __shfl_sync(0xffffffffu, f0, kk);
            a0 += xv * sW[kk * 80 + lane];
            a1 += xv * sW[kk * 80 + 32 + lane];
            a2 += xv * sW[kk * 80 + c2];
        }
#pragma unroll
        for (int kk = 32; kk < 64; kk++) {
            float xv = __shfl_sync(0xffffffffu, f1, kk - 32);
            a0 += xv * sW[kk * 80 + lane];
            a1 += xv * sW[kk * 80 + 32 + lane];
            a2 += xv * sW[kk * 80 + c2];
        }
#pragma unroll
        for (int kk = 64; kk < 70; kk++) {
            float xv = __shfl_sync(0xffffffffu, f2, kk - 64);
            a0 += xv * sW[kk * 80 + lane];
            a1 += xv * sW[kk * 80 + 32 + lane];
            a2 += xv * sW[kk * 80 + c2];
        }
        g_xw2[(size_t)n * 80 + lane] = a0;
        g_xw2[(size_t)n * 80 + 32 + lane] = a1;
        if (lane < 16) g_xw2[(size_t)n * 80 + c2] = a2;
    }
}

// ---------------- scores for GAT2 ----------------
__global__ void scores2_k(const float* __restrict__ att2) {
    int i = blockIdx.x * blockDim.x + threadIdx.x;
    if (i >= NN * 8) return;
    int node = i >> 3, h = i & 7;
    const float* xr = g_xw2 + (size_t)node * 80 + h * 10;
    const float* ai = att2 + h * 20;
    float si = 0.f, sj = 0.f;
#pragma unroll
    for (int c = 0; c < 10; c++) { si += xr[c] * ai[c]; sj += xr[c] * ai[10 + c]; }
    g_s2dst[i] = si;
    g_s2src[i] = sj;
}

// ---------------- GAT2 aggregation (single pass) + mean heads + log_softmax ----------------
__global__ __launch_bounds__(256) void gat2_agg_k(const float* __restrict__ b2,
                                                  float* __restrict__ out) {
    __shared__ float sacc[8][80];
    __shared__ float sval[8][16];
    int gw = (blockIdx.x * blockDim.x + threadIdx.x) >> 5;
    if (gw >= NN) return;
    int lane = threadIdx.x & 31;
    int w = (threadIdx.x >> 5);
    int d = gw;
    int start = g_rowptr[d], deg = g_rowptr[d + 1] - start;
    int hl = lane & 7;
    int eidx = lane >> 3;
    float sdd = g_s2dst[d * 8 + hl];
    float eself = __expf(leaky(sdd + g_s2src[d * 8 + hl]));
    float den = (eidx == 0) ? eself : 0.f;
    int h0 = lane / 10;
    int h1 = (lane + 32) / 10;
    int h2 = (lane + 64) / 10;
    int i2 = 64 + (lane & 15);
    float ws0 = __shfl_sync(0xffffffffu, eself, h0);
    float ws1 = __shfl_sync(0xffffffffu, eself, h1);
    float ws2 = __shfl_sync(0xffffffffu, eself, h2);
    const float* xd = &g_xw2[(size_t)d * 80];
    float acc0 = ws0 * xd[lane];
    float acc1 = ws1 * xd[32 + lane];
    float acc2 = ws2 * xd[i2];
    for (int base = 0; base < deg; base += 4) {
        int e = base + eidx;
        float wv = 0.f;
        int scol = 0;
        if (e < deg) {
            scol = g_col[start + e];
            wv = __expf(leaky(sdd + g_s2src[scol * 8 + hl]));
        }
        den += wv;
#pragma unroll
        for (int i = 0; i < 4; i++) {
            if (base + i < deg) {
                int s = __shfl_sync(0xffffffffu, scol, i * 8);
                float w0 = __shfl_sync(0xffffffffu, wv, i * 8 + h0);
                float w1 = __shfl_sync(0xffffffffu, wv, i * 8 + h1);
                float w2 = __shfl_sync(0xffffffffu, wv, i * 8 + h2);
                const float* xr = &g_xw2[(size_t)s * 80];
                acc0 += w0 * xr[lane];
                acc1 += w1 * xr[32 + lane];
                acc2 += w2 * xr[i2];
            }
        }
    }
    den += __shfl_xor_sync(0xffffffffu, den, 8);
    den += __shfl_xor_sync(0xffffffffu, den, 16);
    float invden = 1.f / den;                      // per lane: head hl
    float iv0 = __shfl_sync(0xffffffffu, invden, h0);
    float iv1 = __shfl_sync(0xffffffffu, invden, h1);
    float iv2 = __shfl_sync(0xffffffffu, invden, h2);
    sacc[w][lane] = acc0 * iv0;
    sacc[w][32 + lane] = acc1 * iv1;
    if (lane < 16) sacc[w][i2] = acc2 * iv2;
    __syncwarp();
    if (lane < 10) {
        float s = 0.f;
#pragma unroll
        for (int h = 0; h < 8; h++) s += sacc[w][h * 10 + lane];
        sval[w][lane] = s * 0.125f + b2[lane];
    }
    __syncwarp();
    if (lane < 10) {
        float mx = -INFINITY;
#pragma unroll
        for (int c = 0; c < 10; c++) mx = fmaxf(mx, sval[w][c]);
        float se = 0.f;
#pragma unroll
        for (int c = 0; c < 10; c++) se += __expf(sval[w][c] - mx);
        out[(size_t)d * 10 + lane] = sval[w][lane] - mx - logf(se);
    }
}

// ---------------- launch ----------------
extern "C" void kernel_launch(void* const* d_in, const int* in_sizes, int n_in,
                              void* d_out, int out_size) {
    const float* x    = (const float*)d_in[0];
    const int*   ei   = (const int*)d_in[1];
    const float* ef   = (const float*)d_in[2];
    const float* W1   = (const float*)d_in[3];
    const float* att1 = (const float*)d_in[4];
    const float* b1   = (const float*)d_in[5];
    const float* W2   = (const float*)d_in[6];
    const float* att2 = (const float*)d_in[7];
    const float* b2   = (const float*)d_in[8];
    const float* Wq   = (const float*)d_in[9];
    const float* bq   = (const float*)d_in[10];
    const float* Wk   = (const float*)d_in[11];
    const float* bk   = (const float*)d_in[12];
    const float* Wv   = (const float*)d_in[13];
    const float* bv   = (const float*)d_in[14];
    const float* g0   = (const float*)d_in[15];
    const float* be0  = (const float*)d_in[16];
    const float* Wf1  = (const float*)d_in[17];
    const float* bf1  = (const float*)d_in[18];
    const float* Wf2  = (const float*)d_in[19];
    const float* bf2  = (const float*)d_in[20];
    const float* g1   = (const float*)d_in[21];
    const float* be1  = (const float*)d_in[22];
    const float* Wrep = (const float*)d_in[23];
    const float* brep = (const float*)d_in[24];
    float* out = (float*)d_out;
    int E = in_sizes[1] / 2;

    zero_deg_k<<<(NN + 255) / 256, 256>>>();
    hist_k<<<(E + 255) / 256, 256>>>(ei, E);
    scan1_k<<<(NN + 1023) / 1024, 256>>>();
    scan2_k<<<1, 128>>>((NN + 1023) / 1024);
    scan3_k<<<(NN + 1023) / 1024, 256>>>();
    fill_k<<<(E + 255) / 256, 256>>>(ei, E);

    gemm1_k<<<1184, 256>>>(x, W1, att1);
    encoder_k<<<1184, 256>>>(ef, Wq, bq, Wk, bk, Wv, bv, g0, be0,
                             Wf1, bf1, Wf2, bf2, g1, be1, Wrep, brep);
    gat1_agg_k<<<(NN + 7) / 8, 256>>>(b1);
    gemm2_k<<<1184, 256>>>(W2);
    scores2_k<<<(NN * 8 + 255) / 256, 256>>>(att2);
    gat2_agg_k<<<(NN + 7) / 8, 256>>>(b2, out);
}

// round 5
// speedup vs baseline: 1.1719x; 1.0507x over previous
#include <cuda_runtime.h>
#include <math.h>

#define NN 100000
#define EE 1600000

// ---------------- scratch ----------------
__device__ __align__(16) float g_xw1[NN * 64];   // x @ W1
__device__ __align__(16) float g_feat2[NN * 70]; // [h1(64) | xt(6)]
__device__ __align__(16) float g_xw2[NN * 80];   // feat2 @ W2
__device__ float g_s1src[NN * 8], g_s1dst[NN * 8];
__device__ float g_s2src[NN * 8], g_s2dst[NN * 8];
__device__ int g_deg[NN];
__device__ int g_rowptr[NN + 1];
__device__ int g_pos[NN];
__device__ int g_col[EE];
__device__ int g_bsum[128];

__device__ __forceinline__ float leaky(float a) { return a >= 0.f ? a : 0.2f * a; }

// ---------------- CSR build ----------------
__global__ void zero_deg_k() {
    int i = blockIdx.x * blockDim.x + threadIdx.x;
    if (i < NN) g_deg[i] = 0;
}

__global__ void hist_k(const int* __restrict__ ei, int E) {
    int e = blockIdx.x * blockDim.x + threadIdx.x;
    if (e >= E) return;
    int s = ei[e], d = ei[E + e];
    if (s != d) atomicAdd(&g_deg[d], 1);
}

__global__ void scan1_k() {
    int b = blockIdx.x, t = threadIdx.x;
    int base = b * 1024 + t * 4;
    int s = 0;
#pragma unroll
    for (int j = 0; j < 4; j++) {
        int i = base + j;
        if (i < NN) s += g_deg[i];
    }
    __shared__ int red[256];
    red[t] = s;
    __syncthreads();
    for (int o = 128; o > 0; o >>= 1) {
        if (t < o) red[t] += red[t + o];
        __syncthreads();
    }
    if (t == 0) g_bsum[b] = red[0];
}

__global__ void scan2_k(int nb) {
    __shared__ int s[128];
    int t = threadIdx.x;
    s[t] = (t < nb) ? g_bsum[t] : 0;
    __syncthreads();
    if (t == 0) {
        int run = 0;
        for (int i = 0; i < nb; i++) { int v = s[i]; s[i] = run; run += v; }
        g_rowptr[NN] = run;
    }
    __syncthreads();
    if (t < nb) g_bsum[t] = s[t];
}

__global__ void scan3_k() {
    int b = blockIdx.x, t = threadIdx.x;
    int base = b * 1024 + t * 4;
    int v[4];
    int tot = 0;
#pragma unroll
    for (int j = 0; j < 4; j++) {
        int i = base + j;
        v[j] = (i < NN) ? g_deg[i] : 0;
        tot += v[j];
    }
    __shared__ int sc[256];
    sc[t] = tot;
    __syncthreads();
    for (int o = 1; o < 256; o <<= 1) {
        int x = (t >= o) ? sc[t - o] : 0;
        __syncthreads();
        sc[t] += x;
        __syncthreads();
    }
    int excl = sc[t] - tot + g_bsum[b];
#pragma unroll
    for (int j = 0; j < 4; j++) {
        int i = base + j;
        if (i < NN) { g_rowptr[i] = excl; g_pos[i] = excl; excl += v[j]; }
    }
}

__global__ void fill_k(const int* __restrict__ ei, int E) {
    int e = blockIdx.x * blockDim.x + threadIdx.x;
    if (e >= E) return;
    int s = ei[e], d = ei[E + e];
    if (s != d) {
        int slot = atomicAdd(&g_pos[d], 1);
        g_col[slot] = s;
    }
}

// ---------------- GEMM 1 + fused GAT1 attention scores ----------------
__global__ __launch_bounds__(256) void gemm1_k(const float* __restrict__ x,
                                               const float* __restrict__ W1,
                                               const float* __restrict__ att1) {
    __shared__ __align__(16) float sW[64 * 64];
    __shared__ float sAtt[128];
    for (int i = threadIdx.x; i < 4096; i += 256) sW[i] = W1[i];
    if (threadIdx.x < 128) sAtt[threadIdx.x] = att1[threadIdx.x];
    __syncthreads();
    int lane = threadIdx.x & 31;
    int gw = (blockIdx.x * blockDim.x + threadIdx.x) >> 5;
    int nw = (gridDim.x * blockDim.x) >> 5;
    int h = lane >> 2;          // head for this lane's 2 cols
    int cc = (lane & 3) * 2;    // col within head
    float ai0 = sAtt[h * 16 + cc],     ai1 = sAtt[h * 16 + cc + 1];
    float aj0 = sAtt[h * 16 + 8 + cc], aj1 = sAtt[h * 16 + 8 + cc + 1];
    for (int n = gw; n < NN; n += nw) {
        float2 xr = *(const float2*)&x[n * 64 + lane * 2];
        float a0 = 0.f, a1 = 0.f;
#pragma unroll
        for (int k2 = 0; k2 < 32; k2++) {
            float xa = __shfl_sync(0xffffffffu, xr.x, k2);
            float xb = __shfl_sync(0xffffffffu, xr.y, k2);
            float2 w0 = *(const float2*)&sW[(2 * k2) * 64 + lane * 2];
            a0 += xa * w0.x; a1 += xa * w0.y;
            float2 w1 = *(const float2*)&sW[(2 * k2 + 1) * 64 + lane * 2];
            a0 += xb * w1.x; a1 += xb * w1.y;
        }
        *(float2*)&g_xw1[n * 64 + lane * 2] = make_float2(a0, a1);
        float si = a0 * ai0 + a1 * ai1;
        float sj = a0 * aj0 + a1 * aj1;
        si += __shfl_xor_sync(0xffffffffu, si, 1);
        si += __shfl_xor_sync(0xffffffffu, si, 2);
        sj += __shfl_xor_sync(0xffffffffu, sj, 1);
        sj += __shfl_xor_sync(0xffffffffu, sj, 2);
        if ((lane & 3) == 0) {
            g_s1dst[n * 8 + h] = si;
            g_s1src[n * 8 + h] = sj;
        }
    }
}

// ---------------- Encoder: warp per node ----------------
__device__ __forceinline__ void ln6(float* o, const float* swf, int goff, int boff) {
    float mu = (o[0] + o[1] + o[2] + o[3] + o[4] + o[5]) * (1.f / 6.f);
    float d0 = o[0] - mu, d1 = o[1] - mu, d2 = o[2] - mu, d3 = o[3] - mu, d4 = o[4] - mu, d5 = o[5] - mu;
    float var = (d0 * d0 + d1 * d1 + d2 * d2 + d3 * d3 + d4 * d4 + d5 * d5) * (1.f / 6.f);
    float rs = rsqrtf(var + 1e-5f);
    o[0] = d0 * rs * swf[goff + 0] + swf[boff + 0];
    o[1] = d1 * rs * swf[goff + 1] + swf[boff + 1];
    o[2] = d2 * rs * swf[goff + 2] + swf[boff + 2];
    o[3] = d3 * rs * swf[goff + 3] + swf[boff + 3];
    o[4] = d4 * rs * swf[goff + 4] + swf[boff + 4];
    o[5] = d5 * rs * swf[goff + 5] + swf[boff + 5];
}

// smem weight layout unchanged (see round 1 comments)
__global__ __launch_bounds__(256) void encoder_k(
    const float* __restrict__ ef,
    const float* __restrict__ Wq, const float* __restrict__ bq,
    const float* __restrict__ Wk, const float* __restrict__ bk,
    const float* __restrict__ Wv, const float* __restrict__ bv,
    const float* __restrict__ g0, const float* __restrict__ be0,
    const float* __restrict__ Wf1, const float* __restrict__ bf1,
    const float* __restrict__ Wf2, const float* __restrict__ bf2,
    const float* __restrict__ g1, const float* __restrict__ be1,
    const float* __restrict__ Wrep, const float* __restrict__ brep) {
    __shared__ __align__(16) float swf[688];
    __shared__ float4 sKV[8][32][3];   // {k0..k3},{k4,k5,v0,v1},{v2..v5}; k pre-scaled
    int tid = threadIdx.x;
    for (int i = tid; i < 688; i += 256) swf[i] = 0.f;
    __syncthreads();
    for (int i = tid; i < 60; i += 256) {
        int kk = i / 6, j = i % 6;
        swf[kk * 8 + j] = Wq[i];
        swf[80 + kk * 8 + j] = Wk[i];
        swf[160 + kk * 8 + j] = Wv[i];
    }
    for (int i = tid; i < 144; i += 256) swf[240 + i] = Wf1[i];
    for (int i = tid; i < 144; i += 256) swf[384 + (i / 6) * 8 + (i % 6)] = Wf2[i];
    if (tid < 6) {
        swf[576 + tid] = bq[tid]; swf[582 + tid] = bk[tid]; swf[588 + tid] = bv[tid];
        swf[594 + tid] = g0[tid]; swf[600 + tid] = be0[tid]; swf[630 + tid] = bf2[tid];
        swf[636 + tid] = g1[tid]; swf[642 + tid] = be1[tid];
    }
    if (tid < 24) swf[606 + tid] = bf1[tid];
    if (tid < 32) swf[648 + tid] = Wrep[tid];
    if (tid == 0) swf[680] = brep[0];
    __syncthreads();

    int lane = tid & 31, w = tid >> 5;
    int gw = (blockIdx.x * blockDim.x + tid) >> 5;
    int nwarps = (gridDim.x * blockDim.x) >> 5;
    const float SCALE = 0.40824829046386307f; // 1/sqrt(6)

    for (int n = gw; n < NN; n += nwarps) {
        const float* xr = ef + (size_t)n * 320 + lane * 10;
        float2 p0 = *(const float2*)xr, p1 = *(const float2*)(xr + 2),
               p2 = *(const float2*)(xr + 4), p3 = *(const float2*)(xr + 6),
               p4 = *(const float2*)(xr + 8);
        float xa[10] = {p0.x, p0.y, p1.x, p1.y, p2.x, p2.y, p3.x, p3.y, p4.x, p4.y};
        float q[6], k[6], v[6];
#pragma unroll
        for (int j = 0; j < 6; j++) { q[j] = swf[576 + j]; k[j] = swf[582 + j]; v[j] = swf[588 + j]; }
#pragma unroll
        for (int kk = 0; kk < 10; kk++) {
            float xv = xa[kk];
            float4 a = *(const float4*)&swf[kk * 8], b4 = *(const float4*)&swf[kk * 8 + 4];
            q[0] += xv * a.x; q[1] += xv * a.y; q[2] += xv * a.z; q[3] += xv * a.w;
            q[4] += xv * b4.x; q[5] += xv * b4.y;
            float4 c = *(const float4*)&swf[80 + kk * 8], d4 = *(const float4*)&swf[80 + kk * 8 + 4];
            k[0] += xv * c.x; k[1] += xv * c.y; k[2] += xv * c.z; k[3] += xv * c.w;
            k[4] += xv * d4.x; k[5] += xv * d4.y;
            float4 e4 = *(const float4*)&swf[160 + kk * 8], f4 = *(const float4*)&swf[160 + kk * 8 + 4];
            v[0] += xv * e4.x; v[1] += xv * e4.y; v[2] += xv * e4.z; v[3] += xv * e4.w;
            v[4] += xv * f4.x; v[5] += xv * f4.y;
        }
        sKV[w][lane][0] = make_float4(k[0] * SCALE, k[1] * SCALE, k[2] * SCALE, k[3] * SCALE);
        sKV[w][lane][1] = make_float4(k[4] * SCALE, k[5] * SCALE, v[0], v[1]);
        sKV[w][lane][2] = make_float4(v[2], v[3], v[4], v[5]);
        __syncwarp();
        float o[6];
        {
            float q0 = q[0], q1 = q[1], q2 = q[2], q3 = q[3], q4 = q[4], q5 = q[5];
            float l0 = 0.f, a00 = 0.f, a01 = 0.f, a02 = 0.f;
            float l1 = 0.f, a10 = 0.f, a11 = 0.f, a12 = 0.f;
#pragma unroll
            for (int tp = 0; tp < 32; tp++) {
                float4 c0 = sKV[w][tp][0];
                float4 c1 = sKV[w][tp][1];
                float4 c2 = sKV[w][tp][2];
                float s0 = q0 * c0.x + q1 * c0.y + q2 * c0.z;
                float s1 = q3 * c0.w + q4 * c1.x + q5 * c1.y;
                float e0 = __expf(s0);
                float e1 = __expf(s1);
                l0 += e0; a00 += e0 * c1.z; a01 += e0 * c1.w; a02 += e0 * c2.x;
                l1 += e1; a10 += e1 * c2.y; a11 += e1 * c2.z; a12 += e1 * c2.w;
            }
            float i0 = 1.f / l0, i1 = 1.f / l1;
            o[0] = q0 + a00 * i0;
            o[1] = q1 + a01 * i0;
            o[2] = q2 + a02 * i0;
            o[3] = q3 + a10 * i1;
            o[4] = q4 + a11 * i1;
            o[5] = q5 + a12 * i1;
        }
        __syncwarp();
        ln6(o, swf, 594, 600);
        float hh_[24];
#pragma unroll
        for (int jj = 0; jj < 24; jj++) hh_[jj] = swf[606 + jj];
#pragma unroll
        for (int kk = 0; kk < 6; kk++) {
            float ov = o[kk];
            const float4* r = (const float4*)&swf[240 + kk * 24];
#pragma unroll
            for (int qq = 0; qq < 6; qq++) {
                float4 wv = r[qq];
                hh_[qq * 4 + 0] += ov * wv.x;
                hh_[qq * 4 + 1] += ov * wv.y;
                hh_[qq * 4 + 2] += ov * wv.z;
                hh_[qq * 4 + 3] += ov * wv.w;
            }
        }
#pragma unroll
        for (int jj = 0; jj < 24; jj++) hh_[jj] = fmaxf(hh_[jj], 0.f);
        float f[6];
#pragma unroll
        for (int j = 0; j < 6; j++) f[j] = swf[630 + j];
#pragma unroll
        for (int jj = 0; jj < 24; jj++) {
            float hv = hh_[jj];
            float4 lo = *(const float4*)&swf[384 + jj * 8];
            float4 hi = *(const float4*)&swf[384 + jj * 8 + 4];
            f[0] += hv * lo.x; f[1] += hv * lo.y; f[2] += hv * lo.z; f[3] += hv * lo.w;
            f[4] += hv * hi.x; f[5] += hv * hi.y;
        }
#pragma unroll
        for (int j = 0; j < 6; j++) o[j] += f[j];
        ln6(o, swf, 636, 642);
        float wr = swf[648 + lane];
        float brepv = swf[680];
#pragma unroll
        for (int j = 0; j < 6; j++) {
            float c = o[j] * wr;
            c += __shfl_xor_sync(0xffffffffu, c, 16);
            c += __shfl_xor_sync(0xffffffffu, c, 8);
            c += __shfl_xor_sync(0xffffffffu, c, 4);
            c += __shfl_xor_sync(0xffffffffu, c, 2);
            c += __shfl_xor_sync(0xffffffffu, c, 1);
            if (lane == 0) g_feat2[(size_t)n * 70 + 64 + j] = c + brepv;
        }
    }
}

// ---------------- GAT1 aggregation: single pass, no max, deferred normalize ----------------
__global__ __launch_bounds__(256) void gat1_agg_k(const float* __restrict__ b1) {
    int gw = (blockIdx.x * blockDim.x + threadIdx.x) >> 5;
    if (gw >= NN) return;
    int lane = threadIdx.x & 31;
    int d = gw;
    int start = g_rowptr[d], deg = g_rowptr[d + 1] - start;
    int hl = lane & 7;        // head for gather lanes (4 edges x 8 heads)
    int eidx = lane >> 3;     // edge-in-chunk for gather lanes
    int c0 = lane * 2;        // output cols for this lane
    int hh = lane >> 2;       // head of output cols
    float sdd = g_s1dst[d * 8 + hl];
    float eself = __expf(leaky(sdd + g_s1src[d * 8 + hl]));
    float den = (eidx == 0) ? eself : 0.f;
    float wself = __shfl_sync(0xffffffffu, eself, hh);
    float2 xs = *(const float2*)&g_xw1[(size_t)d * 64 + c0];
    float acc0 = wself * xs.x, acc1 = wself * xs.y;
    for (int base = 0; base < deg; base += 4) {
        int e = base + eidx;
        float wv = 0.f;
        int scol = 0;
        if (e < deg) {
            scol = g_col[start + e];
            wv = __expf(leaky(sdd + g_s1src[scol * 8 + hl]));
        }
        den += wv;
#pragma unroll
        for (int i = 0; i < 4; i++) {
            if (base + i < deg) {
                int s = __shfl_sync(0xffffffffu, scol, i * 8);
                float wgt = __shfl_sync(0xffffffffu, wv, i * 8 + hh);
                float2 xv = *(const float2*)&g_xw1[(size_t)s * 64 + c0];
                acc0 += wgt * xv.x;
                acc1 += wgt * xv.y;
            }
        }
    }
    den += __shfl_xor_sync(0xffffffffu, den, 8);
    den += __shfl_xor_sync(0xffffffffu, den, 16);
    float invden = 1.f / den;                       // per lane: head hl
    float inv = __shfl_sync(0xffffffffu, invden, hh);
    float v0 = acc0 * inv + b1[c0], v1 = acc1 * inv + b1[c0 + 1];
    v0 = v0 > 0.f ? v0 : (__expf(v0) - 1.f);
    v1 = v1 > 0.f ? v1 : (__expf(v1) - 1.f);
    g_feat2[(size_t)d * 70 + c0] = v0;
    g_feat2[(size_t)d * 70 + c0 + 1] = v1;
}

// ---------------- GEMM 2 + fused GAT2 attention scores ----------------
__global__ __launch_bounds__(256) void gemm2_k(const float* __restrict__ W2,
                                               const float* __restrict__ att2) {
    __shared__ float sW[70 * 80];
    __shared__ float sAtt[160];
    __shared__ float srow[8][80];
    for (int i = threadIdx.x; i < 5600; i += 256) sW[i] = W2[i];
    if (threadIdx.x < 160) sAtt[threadIdx.x] = att2[threadIdx.x];
    __syncthreads();
    int lane = threadIdx.x & 31;
    int w = threadIdx.x >> 5;
    int gw = (blockIdx.x * blockDim.x + threadIdx.x) >> 5;
    int nw = (gridDim.x * blockDim.x) >> 5;
    int c2 = 64 + (lane & 15);
    for (int n = gw; n < NN; n += nw) {
        const float* fr = &g_feat2[(size_t)n * 70];
        float f0 = fr[lane];
        float f1 = fr[32 + lane];
        float f2 = (lane < 6) ? fr[64 + lane] : 0.f;
        float a0 = 0.f, a1 = 0.f, a2 = 0.f;
#pragma unroll
        for (int kk = 0; kk < 32; kk++) {
            float xv = __shfl_sync(0xffffffffu, f0, kk);
            a0 += xv * sW[kk * 80 + lane];
            a1 += xv * sW[kk * 80 + 32 + lane];
            a2 += xv * sW[kk * 80 + c2];
        }
#pragma unroll
        for (int kk = 32; kk < 64; kk++) {
            float xv = __shfl_sync(0xffffffffu, f1, kk - 32);
            a0 += xv * sW[kk * 80 + lane];
            a1 += xv * sW[kk * 80 + 32 + lane];
            a2 += xv * sW[kk * 80 + c2];
        }
#pragma unroll
        for (int kk = 64; kk < 70; kk++) {
            float xv = __shfl_sync(0xffffffffu, f2, kk - 64);
            a0 += xv * sW[kk * 80 + lane];
            a1 += xv * sW[kk * 80 + 32 + lane];
            a2 += xv * sW[kk * 80 + c2];
        }
        g_xw2[(size_t)n * 80 + lane] = a0;
        g_xw2[(size_t)n * 80 + 32 + lane] = a1;
        if (lane < 16) g_xw2[(size_t)n * 80 + c2] = a2;
        // fused attention scores for GAT2
        srow[w][lane] = a0;
        srow[w][32 + lane] = a1;
        if (lane < 16) srow[w][c2] = a2;
        __syncwarp();
        if (lane < 16) {
            int h = lane >> 1, part = lane & 1;
            const float* r = srow[w] + h * 10;
            const float* at = sAtt + h * 20 + part * 10;
            float s = 0.f;
#pragma unroll
            for (int c = 0; c < 10; c++) s += r[c] * at[c];
            if (part == 0) g_s2dst[n * 8 + h] = s;
            else           g_s2src[n * 8 + h] = s;
        }
        __syncwarp();
    }
}

// ---------------- GAT2 aggregation (single pass) + mean heads + log_softmax ----------------
__global__ __launch_bounds__(256) void gat2_agg_k(const float* __restrict__ b2,
                                                  float* __restrict__ out) {
    __shared__ float sacc[8][80];
    __shared__ float sval[8][16];
    int gw = (blockIdx.x * blockDim.x + threadIdx.x) >> 5;
    if (gw >= NN) return;
    int lane = threadIdx.x & 31;
    int w = (threadIdx.x >> 5);
    int d = gw;
    int start = g_rowptr[d], deg = g_rowptr[d + 1] - start;
    int hl = lane & 7;
    int eidx = lane >> 3;
    float sdd = g_s2dst[d * 8 + hl];
    float eself = __expf(leaky(sdd + g_s2src[d * 8 + hl]));
    float den = (eidx == 0) ? eself : 0.f;
    int h0 = lane / 10;
    int h1 = (lane + 32) / 10;
    int h2 = (lane + 64) / 10;
    int i2 = 64 + (lane & 15);
    float ws0 = __shfl_sync(0xffffffffu, eself, h0);
    float ws1 = __shfl_sync(0xffffffffu, eself, h1);
    float ws2 = __shfl_sync(0xffffffffu, eself, h2);
    const float* xd = &g_xw2[(size_t)d * 80];
    float acc0 = ws0 * xd[lane];
    float acc1 = ws1 * xd[32 + lane];
    float acc2 = ws2 * xd[i2];
    for (int base = 0; base < deg; base += 4) {
        int e = base + eidx;
        float wv = 0.f;
        int scol = 0;
        if (e < deg) {
            scol = g_col[start + e];
            wv = __expf(leaky(sdd + g_s2src[scol * 8 + hl]));
        }
        den += wv;
#pragma unroll
        for (int i = 0; i < 4; i++) {
            if (base + i < deg) {
                int s = __shfl_sync(0xffffffffu, scol, i * 8);
                float w0 = __shfl_sync(0xffffffffu, wv, i * 8 + h0);
                float w1 = __shfl_sync(0xffffffffu, wv, i * 8 + h1);
                float w2 = __shfl_sync(0xffffffffu, wv, i * 8 + h2);
                const float* xr = &g_xw2[(size_t)s * 80];
                acc0 += w0 * xr[lane];
                acc1 += w1 * xr[32 + lane];
                acc2 += w2 * xr[i2];
            }
        }
    }
    den += __shfl_xor_sync(0xffffffffu, den, 8);
    den += __shfl_xor_sync(0xffffffffu, den, 16);
    float invden = 1.f / den;
    float iv0 = __shfl_sync(0xffffffffu, invden, h0);
    float iv1 = __shfl_sync(0xffffffffu, invden, h1);
    float iv2 = __shfl_sync(0xffffffffu, invden, h2);
    sacc[w][lane] = acc0 * iv0;
    sacc[w][32 + lane] = acc1 * iv1;
    if (lane < 16) sacc[w][i2] = acc2 * iv2;
    __syncwarp();
    if (lane < 10) {
        float s = 0.f;
#pragma unroll
        for (int h = 0; h < 8; h++) s += sacc[w][h * 10 + lane];
        sval[w][lane] = s * 0.125f + b2[lane];
    }
    __syncwarp();
    if (lane < 10) {
        float mx = -INFINITY;
#pragma unroll
        for (int c = 0; c < 10; c++) mx = fmaxf(mx, sval[w][c]);
        float se = 0.f;
#pragma unroll
        for (int c = 0; c < 10; c++) se += __expf(sval[w][c] - mx);
        out[(size_t)d * 10 + lane] = sval[w][lane] - mx - logf(se);
    }
}

// ---------------- launch ----------------
extern "C" void kernel_launch(void* const* d_in, const int* in_sizes, int n_in,
                              void* d_out, int out_size) {
    const float* x    = (const float*)d_in[0];
    const int*   ei   = (const int*)d_in[1];
    const float* ef   = (const float*)d_in[2];
    const float* W1   = (const float*)d_in[3];
    const float* att1 = (const float*)d_in[4];
    const float* b1   = (const float*)d_in[5];
    const float* W2   = (const float*)d_in[6];
    const float* att2 = (const float*)d_in[7];
    const float* b2   = (const float*)d_in[8];
    const float* Wq   = (const float*)d_in[9];
    const float* bq   = (const float*)d_in[10];
    const float* Wk   = (const float*)d_in[11];
    const float* bk   = (const float*)d_in[12];
    const float* Wv   = (const float*)d_in[13];
    const float* bv   = (const float*)d_in[14];
    const float* g0   = (const float*)d_in[15];
    const float* be0  = (const float*)d_in[16];
    const float* Wf1  = (const float*)d_in[17];
    const float* bf1  = (const float*)d_in[18];
    const float* Wf2  = (const float*)d_in[19];
    const float* bf2  = (const float*)d_in[20];
    const float* g1   = (const float*)d_in[21];
    const float* be1  = (const float*)d_in[22];
    const float* Wrep = (const float*)d_in[23];
    const float* brep = (const float*)d_in[24];
    float* out = (float*)d_out;
    int E = in_sizes[1] / 2;

    zero_deg_k<<<(NN + 255) / 256, 256>>>();
    hist_k<<<(E + 255) / 256, 256>>>(ei, E);
    scan1_k<<<(NN + 1023) / 1024, 256>>>();
    scan2_k<<<1, 128>>>((NN + 1023) / 1024);
    scan3_k<<<(NN + 1023) / 1024, 256>>>();
    fill_k<<<(E + 255) / 256, 256>>>(ei, E);

    gemm1_k<<<1184, 256>>>(x, W1, att1);
    encoder_k<<<1184, 256>>>(ef, Wq, bq, Wk, bk, Wv, bv, g0, be0,
                             Wf1, bf1, Wf2, bf2, g1, be1, Wrep, brep);
    gat1_agg_k<<<(NN + 7) / 8, 256>>>(b1);
    gemm2_k<<<1184, 256>>>(W2, att2);
    gat2_agg_k<<<(NN + 7) / 8, 256>>>(b2, out);
}